// round 13
// baseline (speedup 1.0000x reference)
#include <cuda_runtime.h>
#include <cuda_bf16.h>
#include <cstdint>

#define N    4096
#define D    2048
#define DL   1024
#define BM   128
#define BN   128
#define KS   64                  // k elems per pipeline stage (4 k16 slices)
#define NSTG (D / KS)            // 32
#define PIPE 3                   // cp.async stages
#define NTILE (N / BN)           // 32
#define NBLK  (NTILE * (NTILE + 1) / 2)  // 528
#define TILE_B   4096            // one 128x16 bf16 sub-tile
#define STAGE_B  (8 * TILE_B)    // {A,B} x {4 k16 slices} = 32 KB
#define DYN_B    (PIPE * STAGE_B)  // 96 KB
#define MARGIN 0.3f
#define EPSC   1e-12f
#define IINF   0x7fffffff

// ---------------- scratch (no allocations allowed) ----------------
__device__ int   g_tgt[N];
__device__ float g_sq[N];
__device__ float g_lsq[N];
__device__ __nv_bfloat16 g_xhi[(size_t)N * D];
__device__ float g_posVal[NTILE * 2 * N];
__device__ int   g_posIdx[NTILE * 2 * N];
__device__ float g_negVal[NTILE * 2 * N];
__device__ int   g_negIdx[NTILE * 2 * N];
__device__ float g_rowLoss[N];
__device__ float g_rowLocal[N];

// ---------------- helpers ----------------
__device__ __forceinline__ unsigned smem_u32(const void* p) {
    unsigned a;
    asm("{ .reg .u64 t; cvta.to.shared.u64 t, %1; cvt.u32.u64 %0, t; }" : "=r"(a) : "l"(p));
    return a;
}
__device__ __forceinline__ void cp16(unsigned dst, const void* src) {
    asm volatile("cp.async.cg.shared.global [%0], [%1], 16;" :: "r"(dst), "l"(src) : "memory");
}
__device__ __forceinline__ void ldsm4(unsigned* r, unsigned addr) {
    asm volatile("ldmatrix.sync.aligned.m8n8.x4.shared.b16 {%0,%1,%2,%3}, [%4];"
        : "=r"(r[0]), "=r"(r[1]), "=r"(r[2]), "=r"(r[3]) : "r"(addr));
}
__device__ __forceinline__ void mma16816(float* c, const unsigned* a, unsigned b0, unsigned b1) {
    asm volatile("mma.sync.aligned.m16n8k16.row.col.f32.bf16.bf16.f32 "
        "{%0,%1,%2,%3}, {%4,%5,%6,%7}, {%8,%9}, {%0,%1,%2,%3};"
        : "+f"(c[0]), "+f"(c[1]), "+f"(c[2]), "+f"(c[3])
        : "r"(a[0]), "r"(a[1]), "r"(a[2]), "r"(a[3]), "r"(b0), "r"(b1));
}
__device__ __forceinline__ unsigned tswz(int r, int h) {
    return (unsigned)(r * 32 + ((h * 16) ^ ((r & 4) << 2)));
}
// top-2 insert, "smaller is better", tie-break lower index
__device__ __forceinline__ void ins_min(float& v1, int& i1, float& v2, int& i2, float u, int j) {
    if (u < v1 || (u == v1 && j < i1)) { v2 = v1; i2 = i1; v1 = u; i1 = j; }
    else if (u < v2 || (u == v2 && j < i2)) { v2 = u; i2 = j; }
}
// top-2 insert, "larger is better", tie-break lower index
__device__ __forceinline__ void ins_max(float& v1, int& i1, float& v2, int& i2, float u, int j) {
    if (u > v1 || (u == v1 && j < i1)) { v2 = v1; i2 = i1; v1 = u; i1 = j; }
    else if (u > v2 || (u == v2 && j < i2)) { v2 = u; i2 = j; }
}
#define SHFL_MERGE2(INS, v1, i1, v2, i2, off) do { \
    float _ov1 = __shfl_xor_sync(0xffffffffu, v1, off); \
    int   _oi1 = __shfl_xor_sync(0xffffffffu, i1, off); \
    float _ov2 = __shfl_xor_sync(0xffffffffu, v2, off); \
    int   _oi2 = __shfl_xor_sync(0xffffffffu, i2, off); \
    INS(v1, i1, v2, i2, _ov1, _oi1); \
    INS(v1, i1, v2, i2, _ov2, _oi2); \
} while (0)

// ---------------- kernel 0: normalize targets (int32 vs int64 autodetect) ----
__global__ void prep_targets(const int* __restrict__ T32) {
    int f = 0;
    for (int i = threadIdx.x; i < N / 2; i += blockDim.x) f |= T32[2 * i + 1];
    int any = __syncthreads_or(f);
    bool is64 = (any == 0);
    for (int i = threadIdx.x; i < N; i += blockDim.x)
        g_tgt[i] = is64 ? T32[2 * i] : T32[i];
}

// ---------------- kernel 1: bf16 hi of X + row norms ------------------------
__global__ void convert_kernel(const float* __restrict__ X) {
    int row = blockIdx.x;
    int t = threadIdx.x;
    const float* src = X + (size_t)row * D;
    float s = 0.f;
    for (int k = t * 4; k < D; k += 256 * 4) {
        float4 v = *(const float4*)(src + k);
        s += v.x * v.x + v.y * v.y + v.z * v.z + v.w * v.w;
        unsigned h0 = (unsigned)__bfloat16_as_ushort(__float2bfloat16(v.x));
        unsigned h1 = (unsigned)__bfloat16_as_ushort(__float2bfloat16(v.y));
        unsigned h2 = (unsigned)__bfloat16_as_ushort(__float2bfloat16(v.z));
        unsigned h3 = (unsigned)__bfloat16_as_ushort(__float2bfloat16(v.w));
        *(uint2*)&g_xhi[(size_t)row * D + k] = make_uint2(h0 | (h1 << 16), h2 | (h3 << 16));
    }
    __shared__ float red[256];
    red[t] = s;
    __syncthreads();
    for (int off = 128; off > 0; off >>= 1) {
        if (t < off) red[t] += red[t + off];
        __syncthreads();
    }
    if (t == 0) g_sq[row] = red[0];
}

// ---------------- kernel 1b: local-feature row norms ------------------------
__global__ void lnorms_kernel(const float* __restrict__ XL) {
    int b = blockIdx.x;
    int t = threadIdx.x;
    const float* src = XL + (size_t)b * DL;
    float s = 0.f;
    for (int k = t * 4; k < DL; k += 256 * 4) {
        float4 v = *(const float4*)(src + k);
        s += v.x * v.x + v.y * v.y + v.z * v.z + v.w * v.w;
    }
    __shared__ float red[256];
    red[t] = s;
    __syncthreads();
    for (int off = 128; off > 0; off >>= 1) {
        if (t < off) red[t] += red[t + off];
        __syncthreads();
    }
    if (t == 0) g_lsq[b] = red[0];
}

// ---------------- kernel 2: 1-GEMM approx Gram + top-2 dual mining ----------
// Mining compares SQUARED distances (sqrt is monotone; exact refinement in
// finalize_rows re-ranks with reference sqrt + tie-break).
__global__ __launch_bounds__(256, 2)
void gram_mma_kernel() {
    int kblk = blockIdx.x;
    int bx = (int)((sqrtf(8.0f * (float)kblk + 1.0f) - 1.0f) * 0.5f);
    while (bx * (bx + 1) / 2 > kblk) bx--;
    while ((bx + 1) * (bx + 2) / 2 <= kblk) bx++;
    int by = kblk - bx * (bx + 1) / 2;
    int rowBase = by * BM, colBase = bx * BN;
    bool diag = (bx == by);

    extern __shared__ char dyn[];
    __shared__ float sqR[BM], sqC[BN];
    __shared__ int   tgtR[BM], tgtC[BN];
    __shared__ float rPV[4][2][128], rNV[4][2][128];
    __shared__ int   rPI[4][2][128], rNI[4][2][128];
    __shared__ float cPV[2][2][128], cNV[2][2][128];
    __shared__ int   cPI[2][2][128], cNI[2][2][128];

    int t = threadIdx.x, wid = t >> 5, lid = t & 31;
    int wy = wid >> 2, wx = wid & 3;           // 2 x 4 warp grid
    int warpRow = wy * 64, warpCol = wx * 32;  // warp tile 64 x 32
    unsigned sbase = smem_u32(dyn);

    if (t < 128) {
        sqR[t] = g_sq[rowBase + t]; tgtR[t] = g_tgt[rowBase + t];
        sqC[t] = g_sq[colBase + t]; tgtC[t] = g_tgt[colBase + t];
    }
    __syncthreads();

    const __nv_bfloat16* gsrc[2] = {
        g_xhi + (size_t)rowBase * D, g_xhi + (size_t)colBase * D
    };
    int r0 = t >> 1, h = t & 1;
    unsigned stoff = tswz(r0, h);

    auto issueStage = [&](int j) {
        unsigned sb = sbase + (unsigned)((j % PIPE) * STAGE_B);
        size_t kb = (size_t)j * KS;
#pragma unroll
        for (int op = 0; op < 2; op++) {
#pragma unroll
            for (int ks = 0; ks < 4; ks++) {
                unsigned dst = sb + (unsigned)((op * 4 + ks) * TILE_B) + stoff;
                const void* src = gsrc[op] + (size_t)r0 * D + kb + ks * 16 + h * 8;
                cp16(dst, src);
            }
        }
        asm volatile("cp.async.commit_group;" ::: "memory");
    };

    float C[4][4][4];
#pragma unroll
    for (int mi = 0; mi < 4; mi++)
#pragma unroll
        for (int ni = 0; ni < 4; ni++)
#pragma unroll
            for (int q = 0; q < 4; q++) C[mi][ni][q] = 0.f;

    int sub = lid >> 3, lr = lid & 7;
    unsigned offA[4], offB[2];
#pragma unroll
    for (int mi = 0; mi < 4; mi++)
        offA[mi] = tswz(warpRow + mi * 16 + (sub & 1) * 8 + lr, sub >> 1);
#pragma unroll
    for (int ni2 = 0; ni2 < 2; ni2++)
        offB[ni2] = tswz(warpCol + ni2 * 16 + (sub >> 1) * 8 + lr, sub & 1);

    issueStage(0);
    issueStage(1);

    for (int kt = 0; kt < NSTG; kt++) {
        if (kt + 1 < NSTG) {
            asm volatile("cp.async.wait_group 1;" ::: "memory");
        } else {
            asm volatile("cp.async.wait_group 0;" ::: "memory");
        }
        __syncthreads();
        if (kt + 2 < NSTG) issueStage(kt + 2);

        unsigned base = sbase + (unsigned)((kt % PIPE) * STAGE_B);
#pragma unroll
        for (int ks = 0; ks < 4; ks++) {
            unsigned aT = base + (unsigned)((0 * 4 + ks) * TILE_B);
            unsigned bT = base + (unsigned)((1 * 4 + ks) * TILE_B);
            unsigned ahi[4][4], bh[2][4];
#pragma unroll
            for (int mi = 0; mi < 4; mi++) ldsm4(ahi[mi], aT + offA[mi]);
#pragma unroll
            for (int ni2 = 0; ni2 < 2; ni2++) ldsm4(bh[ni2], bT + offB[ni2]);
#pragma unroll
            for (int mi = 0; mi < 4; mi++)
#pragma unroll
                for (int ni2 = 0; ni2 < 2; ni2++)
#pragma unroll
                    for (int f = 0; f < 2; f++)
                        mma16816(C[mi][ni2 * 2 + f], ahi[mi], bh[ni2][2 * f], bh[ni2][2 * f + 1]);
        }
    }

    // ---- epilogue: top-2 mining on SQUARED distances ----
    // C[mi][ni][rh*2+cb]: row = warpRow + mi*16 + lid/4 + rh*8,
    //                     col = warpCol + ni*8 + (lid%4)*2 + cb
#pragma unroll
    for (int mi = 0; mi < 4; mi++) {
#pragma unroll
        for (int rh = 0; rh < 2; rh++) {
            int lrow = warpRow + mi * 16 + (lid >> 2) + rh * 8;
            float sq = sqR[lrow];
            int tr = tgtR[lrow];
            float pv1 = -1e30f, pv2 = -1e30f; int pi1 = IINF, pi2 = IINF;
            float nv1 =  1e30f, nv2 =  1e30f; int ni1 = IINF, ni2 = IINF;
#pragma unroll
            for (int ni = 0; ni < 4; ni++) {
#pragma unroll
                for (int cb = 0; cb < 2; cb++) {
                    int lcol = warpCol + ni * 8 + (lid & 3) * 2 + cb;
                    float ds = sq + sqC[lcol] - 2.f * C[mi][ni][rh * 2 + cb];
                    int gj = colBase + lcol;
                    if (tr == tgtC[lcol]) {
                        if (!(diag && lrow == lcol)) ins_max(pv1, pi1, pv2, pi2, ds, gj);
                    } else {
                        ins_min(nv1, ni1, nv2, ni2, ds, gj);
                    }
                }
            }
            SHFL_MERGE2(ins_max, pv1, pi1, pv2, pi2, 1);
            SHFL_MERGE2(ins_max, pv1, pi1, pv2, pi2, 2);
            SHFL_MERGE2(ins_min, nv1, ni1, nv2, ni2, 1);
            SHFL_MERGE2(ins_min, nv1, ni1, nv2, ni2, 2);
            if ((lid & 3) == 0) {
                rPV[wx][0][lrow] = pv1; rPI[wx][0][lrow] = pi1;
                rPV[wx][1][lrow] = pv2; rPI[wx][1][lrow] = pi2;
                rNV[wx][0][lrow] = nv1; rNI[wx][0][lrow] = ni1;
                rNV[wx][1][lrow] = nv2; rNI[wx][1][lrow] = ni2;
            }
        }
    }
    __syncthreads();
    if (t < 128) {
        float pv1 = -1e30f, pv2 = -1e30f; int pi1 = IINF, pi2 = IINF;
        float nv1 =  1e30f, nv2 =  1e30f; int ni1 = IINF, ni2 = IINF;
#pragma unroll
        for (int s = 0; s < 4; s++)
#pragma unroll
            for (int e = 0; e < 2; e++) {
                ins_max(pv1, pi1, pv2, pi2, rPV[s][e][t], rPI[s][e][t]);
                ins_min(nv1, ni1, nv2, ni2, rNV[s][e][t], rNI[s][e][t]);
            }
        int r = rowBase + t;
        g_posVal[(bx * 2 + 0) * N + r] = pv1; g_posIdx[(bx * 2 + 0) * N + r] = pi1;
        g_posVal[(bx * 2 + 1) * N + r] = pv2; g_posIdx[(bx * 2 + 1) * N + r] = pi2;
        g_negVal[(bx * 2 + 0) * N + r] = nv1; g_negIdx[(bx * 2 + 0) * N + r] = ni1;
        g_negVal[(bx * 2 + 1) * N + r] = nv2; g_negIdx[(bx * 2 + 1) * N + r] = ni2;
    }

    if (!diag) {
        __syncthreads();
#pragma unroll
        for (int ni = 0; ni < 4; ni++) {
#pragma unroll
            for (int cb = 0; cb < 2; cb++) {
                int lcol = warpCol + ni * 8 + (lid & 3) * 2 + cb;
                float sqc = sqC[lcol];
                int tc = tgtC[lcol];
                float pv1 = -1e30f, pv2 = -1e30f; int pi1 = IINF, pi2 = IINF;
                float nv1 =  1e30f, nv2 =  1e30f; int ni1 = IINF, ni2 = IINF;
#pragma unroll
                for (int mi = 0; mi < 4; mi++) {
#pragma unroll
                    for (int rh = 0; rh < 2; rh++) {
                        int lrow = warpRow + mi * 16 + (lid >> 2) + rh * 8;
                        float ds = sqR[lrow] + sqc - 2.f * C[mi][ni][rh * 2 + cb];
                        int gi = rowBase + lrow;
                        if (tc == tgtR[lrow]) ins_max(pv1, pi1, pv2, pi2, ds, gi);
                        else                  ins_min(nv1, ni1, nv2, ni2, ds, gi);
                    }
                }
                SHFL_MERGE2(ins_max, pv1, pi1, pv2, pi2, 4);
                SHFL_MERGE2(ins_max, pv1, pi1, pv2, pi2, 8);
                SHFL_MERGE2(ins_max, pv1, pi1, pv2, pi2, 16);
                SHFL_MERGE2(ins_min, nv1, ni1, nv2, ni2, 4);
                SHFL_MERGE2(ins_min, nv1, ni1, nv2, ni2, 8);
                SHFL_MERGE2(ins_min, nv1, ni1, nv2, ni2, 16);
                if (lid < 4) {
                    cPV[wy][0][lcol] = pv1; cPI[wy][0][lcol] = pi1;
                    cPV[wy][1][lcol] = pv2; cPI[wy][1][lcol] = pi2;
                    cNV[wy][0][lcol] = nv1; cNI[wy][0][lcol] = ni1;
                    cNV[wy][1][lcol] = nv2; cNI[wy][1][lcol] = ni2;
                }
            }
        }
        __syncthreads();
        if (t < 128) {
            float pv1 = -1e30f, pv2 = -1e30f; int pi1 = IINF, pi2 = IINF;
            float nv1 =  1e30f, nv2 =  1e30f; int ni1 = IINF, ni2 = IINF;
#pragma unroll
            for (int s = 0; s < 2; s++)
#pragma unroll
                for (int e = 0; e < 2; e++) {
                    ins_max(pv1, pi1, pv2, pi2, cPV[s][e][t], cPI[s][e][t]);
                    ins_min(nv1, ni1, nv2, ni2, cNV[s][e][t], cNI[s][e][t]);
                }
            int r = colBase + t;
            g_posVal[(by * 2 + 0) * N + r] = pv1; g_posIdx[(by * 2 + 0) * N + r] = pi1;
            g_posVal[(by * 2 + 1) * N + r] = pv2; g_posIdx[(by * 2 + 1) * N + r] = pi2;
            g_negVal[(by * 2 + 0) * N + r] = nv1; g_negIdx[(by * 2 + 0) * N + r] = ni1;
            g_negVal[(by * 2 + 1) * N + r] = nv2; g_negIdx[(by * 2 + 1) * N + r] = ni2;
        }
    }
}

// ---------------- kernel 3: top-4 select + exact fp32 refine + local --------
__device__ __forceinline__ float warpDot(const float* a, const float* b, int lane) {
    float s = 0.f;
    for (int k = lane * 4; k < D; k += 128) {
        float4 x = *(const float4*)(a + k);
        float4 y = *(const float4*)(b + k);
        s += x.x * y.x + x.y * y.y + x.z * y.z + x.w * y.w;
    }
#pragma unroll
    for (int off = 16; off > 0; off >>= 1)
        s += __shfl_xor_sync(0xffffffffu, s, off);
    return s;
}

__global__ void finalize_rows(const float* __restrict__ X, const float* __restrict__ XL) {
    int warp = (blockIdx.x * blockDim.x + threadIdx.x) >> 5;
    int lane = threadIdx.x & 31;
    if (warp >= N) return;
    int row = warp;

    float pv[2], nvv[2]; int pidx[2], nidx[2];
#pragma unroll
    for (int e = 0; e < 2; e++) {
        pv[e]   = g_posVal[(lane * 2 + e) * N + row];
        pidx[e] = g_posIdx[(lane * 2 + e) * N + row];
        nvv[e]  = g_negVal[(lane * 2 + e) * N + row];
        nidx[e] = g_negIdx[(lane * 2 + e) * N + row];
    }

    int nsel[4];
#pragma unroll
    for (int it = 0; it < 4; it++) {
        float bv = 1e30f; int bi = IINF;
#pragma unroll
        for (int e = 0; e < 2; e++)
            if (nvv[e] < bv || (nvv[e] == bv && nidx[e] < bi)) { bv = nvv[e]; bi = nidx[e]; }
#pragma unroll
        for (int off = 16; off > 0; off >>= 1) {
            float ov = __shfl_xor_sync(0xffffffffu, bv, off);
            int   oi = __shfl_xor_sync(0xffffffffu, bi, off);
            if (ov < bv || (ov == bv && oi < bi)) { bv = ov; bi = oi; }
        }
        nsel[it] = bi;
#pragma unroll
        for (int e = 0; e < 2; e++)
            if (nidx[e] == bi) { nvv[e] = 1e30f; nidx[e] = IINF; }
    }
    int psel[4];
#pragma unroll
    for (int it = 0; it < 4; it++) {
        float bv = -1e30f; int bi = IINF;
#pragma unroll
        for (int e = 0; e < 2; e++)
            if (pv[e] > bv || (pv[e] == bv && pidx[e] < bi)) { bv = pv[e]; bi = pidx[e]; }
#pragma unroll
        for (int off = 16; off > 0; off >>= 1) {
            float ov = __shfl_xor_sync(0xffffffffu, bv, off);
            int   oi = __shfl_xor_sync(0xffffffffu, bi, off);
            if (ov > bv || (ov == bv && oi < bi)) { bv = ov; bi = oi; }
        }
        psel[it] = bi;
#pragma unroll
        for (int e = 0; e < 2; e++)
            if (pidx[e] == bi) { pv[e] = -1e30f; pidx[e] = IINF; }
    }

    const float* xr = X + (size_t)row * D;
    float sqr = g_sq[row];
    float bestPd = -1e30f; int bestPi = IINF;
#pragma unroll
    for (int it = 0; it < 4; it++) {
        int j = psel[it];
        if (j < 0 || j >= N) continue;
        float dot = warpDot(xr, X + (size_t)j * D, lane);
        float d = sqrtf(fmaxf(sqr + g_sq[j] - 2.f * dot, EPSC));
        if (d > bestPd || (d == bestPd && j < bestPi)) { bestPd = d; bestPi = j; }
    }
    float bestNd = 1e30f; int bestNi = IINF;
#pragma unroll
    for (int it = 0; it < 4; it++) {
        int j = nsel[it];
        if (j < 0 || j >= N) continue;
        float dot = warpDot(xr, X + (size_t)j * D, lane);
        float d = sqrtf(fmaxf(sqr + g_sq[j] - 2.f * dot, EPSC));
        if (d < bestNd || (d == bestNd && j < bestNi)) { bestNd = d; bestNi = j; }
    }
    int pi = (bestPi < 0 || bestPi >= N) ? row : bestPi;
    int ni = (bestNi < 0 || bestNi >= N) ? row : bestNi;

    const float* li = XL + (size_t)row * DL;
    const float* lp = XL + (size_t)pi  * DL;
    const float* ln = XL + (size_t)ni  * DL;
    float dp = 0.f, dn = 0.f;
    for (int k = lane * 4; k < DL; k += 128) {
        float4 a = *(const float4*)(li + k);
        float4 b = *(const float4*)(lp + k);
        float4 c = *(const float4*)(ln + k);
        dp += a.x * b.x + a.y * b.y + a.z * b.z + a.w * b.w;
        dn += a.x * c.x + a.y * c.y + a.z * c.z + a.w * c.w;
    }
#pragma unroll
    for (int off = 16; off > 0; off >>= 1) {
        dp += __shfl_xor_sync(0xffffffffu, dp, off);
        dn += __shfl_xor_sync(0xffffffffu, dn, off);
    }
    if (lane == 0) {
        float lap = sqrtf(fmaxf(g_lsq[row] + g_lsq[pi] - 2.f * dp, EPSC));
        float lan = sqrtf(fmaxf(g_lsq[row] + g_lsq[ni] - 2.f * dn, EPSC));
        g_rowLoss[row]  = fmaxf(0.f, bestPd - bestNd + MARGIN);
        g_rowLocal[row] = fmaxf(0.f, lap - lan + MARGIN);
    }
}

// ---------------- kernel 4: deterministic means ----------------
__global__ void final_reduce(float* __restrict__ out, int out_size) {
    __shared__ float s1[256], s2[256];
    int t = threadIdx.x;
    float a = 0.f, b = 0.f;
    for (int i = t; i < N; i += 256) { a += g_rowLoss[i]; b += g_rowLocal[i]; }
    s1[t] = a; s2[t] = b;
    __syncthreads();
    for (int off = 128; off > 0; off >>= 1) {
        if (t < off) { s1[t] += s1[t + off]; s2[t] += s2[t + off]; }
        __syncthreads();
    }
    if (t == 0) {
        out[0] = s1[0] / (float)N;
        if (out_size > 1) out[1] = s2[0] / (float)N;
    }
}

// ---------------- launch ----------------
extern "C" void kernel_launch(void* const* d_in, const int* in_sizes, int n_in,
                              void* d_out, int out_size) {
    const float* X  = (const float*)d_in[0];
    const float* XL = (const float*)d_in[1];
    const int*   T  = (const int*)d_in[2];
    (void)in_sizes; (void)n_in;

    cudaFuncSetAttribute(gram_mma_kernel,
                         cudaFuncAttributeMaxDynamicSharedMemorySize, DYN_B);

    prep_targets<<<1, 1024>>>(T);
    convert_kernel<<<N, 256>>>(X);
    lnorms_kernel<<<N, 256>>>(XL);
    gram_mma_kernel<<<NBLK, 256, DYN_B>>>();
    finalize_rows<<<N / 8, 256>>>(X, XL);
    final_reduce<<<1, 256>>>((float*)d_out, out_size);
}

// round 14
// speedup vs baseline: 1.4000x; 1.4000x over previous
#include <cuda_runtime.h>
#include <cuda_bf16.h>
#include <cstdint>

#define N    4096
#define D    2048
#define DL   1024
#define BM   128
#define BN   128
#define KS   64                  // k elems per pipeline stage (4 k16 slices)
#define NSTG (D / KS)            // 32
#define PIPE 2                   // double buffer
#define NTILE (N / BN)           // 32
#define NBLK  (NTILE * (NTILE + 1) / 2)  // 528
#define TILE_B   4096            // one 128x16 bf16 sub-tile
#define STAGE_B  (8 * TILE_B)    // {A,B} x {4 k16 slices} = 32 KB
#define DYN_B    (PIPE * STAGE_B)  // 64 KB -> 2 blocks/SM with ~27 KB static
#define MARGIN 0.3f
#define EPSC   1e-12f
#define IINF   0x7fffffff

// ---------------- scratch (no allocations allowed) ----------------
__device__ int   g_tgt[N];
__device__ float g_sq[N];
__device__ float g_lsq[N];
__device__ __nv_bfloat16 g_xhi[(size_t)N * D];
__device__ float g_posVal[NTILE * 2 * N];
__device__ int   g_posIdx[NTILE * 2 * N];
__device__ float g_negVal[NTILE * 2 * N];
__device__ int   g_negIdx[NTILE * 2 * N];
__device__ float g_rowLoss[N];
__device__ float g_rowLocal[N];

// ---------------- helpers ----------------
__device__ __forceinline__ unsigned smem_u32(const void* p) {
    unsigned a;
    asm("{ .reg .u64 t; cvta.to.shared.u64 t, %1; cvt.u32.u64 %0, t; }" : "=r"(a) : "l"(p));
    return a;
}
__device__ __forceinline__ void cp16(unsigned dst, const void* src) {
    asm volatile("cp.async.cg.shared.global [%0], [%1], 16;" :: "r"(dst), "l"(src) : "memory");
}
__device__ __forceinline__ void ldsm4(unsigned* r, unsigned addr) {
    asm volatile("ldmatrix.sync.aligned.m8n8.x4.shared.b16 {%0,%1,%2,%3}, [%4];"
        : "=r"(r[0]), "=r"(r[1]), "=r"(r[2]), "=r"(r[3]) : "r"(addr));
}
__device__ __forceinline__ void mma16816(float* c, const unsigned* a, unsigned b0, unsigned b1) {
    asm volatile("mma.sync.aligned.m16n8k16.row.col.f32.bf16.bf16.f32 "
        "{%0,%1,%2,%3}, {%4,%5,%6,%7}, {%8,%9}, {%0,%1,%2,%3};"
        : "+f"(c[0]), "+f"(c[1]), "+f"(c[2]), "+f"(c[3])
        : "r"(a[0]), "r"(a[1]), "r"(a[2]), "r"(a[3]), "r"(b0), "r"(b1));
}
__device__ __forceinline__ unsigned tswz(int r, int h) {
    return (unsigned)(r * 32 + ((h * 16) ^ ((r & 4) << 2)));
}
// top-2 insert, "smaller is better", tie-break lower index
__device__ __forceinline__ void ins_min(float& v1, int& i1, float& v2, int& i2, float u, int j) {
    if (u < v1 || (u == v1 && j < i1)) { v2 = v1; i2 = i1; v1 = u; i1 = j; }
    else if (u < v2 || (u == v2 && j < i2)) { v2 = u; i2 = j; }
}
// top-2 insert, "larger is better", tie-break lower index
__device__ __forceinline__ void ins_max(float& v1, int& i1, float& v2, int& i2, float u, int j) {
    if (u > v1 || (u == v1 && j < i1)) { v2 = v1; i2 = i1; v1 = u; i1 = j; }
    else if (u > v2 || (u == v2 && j < i2)) { v2 = u; i2 = j; }
}
#define SHFL_MERGE2(INS, v1, i1, v2, i2, off) do { \
    float _ov1 = __shfl_xor_sync(0xffffffffu, v1, off); \
    int   _oi1 = __shfl_xor_sync(0xffffffffu, i1, off); \
    float _ov2 = __shfl_xor_sync(0xffffffffu, v2, off); \
    int   _oi2 = __shfl_xor_sync(0xffffffffu, i2, off); \
    INS(v1, i1, v2, i2, _ov1, _oi1); \
    INS(v1, i1, v2, i2, _ov2, _oi2); \
} while (0)

// ---------------- kernel 0: normalize targets (int32 vs int64 autodetect) ----
__global__ void prep_targets(const int* __restrict__ T32) {
    int f = 0;
    for (int i = threadIdx.x; i < N / 2; i += blockDim.x) f |= T32[2 * i + 1];
    int any = __syncthreads_or(f);
    bool is64 = (any == 0);
    for (int i = threadIdx.x; i < N; i += blockDim.x)
        g_tgt[i] = is64 ? T32[2 * i] : T32[i];
}

// ---------------- kernel 1: bf16 hi of X + row norms ------------------------
__global__ void convert_kernel(const float* __restrict__ X) {
    int row = blockIdx.x;
    int t = threadIdx.x;
    const float* src = X + (size_t)row * D;
    float s = 0.f;
    for (int k = t * 4; k < D; k += 256 * 4) {
        float4 v = *(const float4*)(src + k);
        s += v.x * v.x + v.y * v.y + v.z * v.z + v.w * v.w;
        unsigned h0 = (unsigned)__bfloat16_as_ushort(__float2bfloat16(v.x));
        unsigned h1 = (unsigned)__bfloat16_as_ushort(__float2bfloat16(v.y));
        unsigned h2 = (unsigned)__bfloat16_as_ushort(__float2bfloat16(v.z));
        unsigned h3 = (unsigned)__bfloat16_as_ushort(__float2bfloat16(v.w));
        *(uint2*)&g_xhi[(size_t)row * D + k] = make_uint2(h0 | (h1 << 16), h2 | (h3 << 16));
    }
    __shared__ float red[256];
    red[t] = s;
    __syncthreads();
    for (int off = 128; off > 0; off >>= 1) {
        if (t < off) red[t] += red[t + off];
        __syncthreads();
    }
    if (t == 0) g_sq[row] = red[0];
}

// ---------------- kernel 1b: local-feature row norms ------------------------
__global__ void lnorms_kernel(const float* __restrict__ XL) {
    int b = blockIdx.x;
    int t = threadIdx.x;
    const float* src = XL + (size_t)b * DL;
    float s = 0.f;
    for (int k = t * 4; k < DL; k += 256 * 4) {
        float4 v = *(const float4*)(src + k);
        s += v.x * v.x + v.y * v.y + v.z * v.z + v.w * v.w;
    }
    __shared__ float red[256];
    red[t] = s;
    __syncthreads();
    for (int off = 128; off > 0; off >>= 1) {
        if (t < off) red[t] += red[t + off];
        __syncthreads();
    }
    if (t == 0) g_lsq[b] = red[0];
}

// ---------------- kernel 2: 1-GEMM approx Gram + top-2 dual mining ----------
// Mining compares SQUARED distances (sqrt is monotone; exact refinement in
// finalize_rows re-ranks with reference sqrt + tie-break).
// Double-buffered KS=64 stages: 32 barriers/tile at 2 blocks/SM.
__global__ __launch_bounds__(256, 2)
void gram_mma_kernel() {
    int kblk = blockIdx.x;
    int bx = (int)((sqrtf(8.0f * (float)kblk + 1.0f) - 1.0f) * 0.5f);
    while (bx * (bx + 1) / 2 > kblk) bx--;
    while ((bx + 1) * (bx + 2) / 2 <= kblk) bx++;
    int by = kblk - bx * (bx + 1) / 2;
    int rowBase = by * BM, colBase = bx * BN;
    bool diag = (bx == by);

    extern __shared__ char dyn[];
    __shared__ float sqR[BM], sqC[BN];
    __shared__ int   tgtR[BM], tgtC[BN];
    __shared__ float rPV[4][2][128], rNV[4][2][128];
    __shared__ int   rPI[4][2][128], rNI[4][2][128];
    __shared__ float cPV[2][2][128], cNV[2][2][128];
    __shared__ int   cPI[2][2][128], cNI[2][2][128];

    int t = threadIdx.x, wid = t >> 5, lid = t & 31;
    int wy = wid >> 2, wx = wid & 3;           // 2 x 4 warp grid
    int warpRow = wy * 64, warpCol = wx * 32;  // warp tile 64 x 32
    unsigned sbase = smem_u32(dyn);

    if (t < 128) {
        sqR[t] = g_sq[rowBase + t]; tgtR[t] = g_tgt[rowBase + t];
        sqC[t] = g_sq[colBase + t]; tgtC[t] = g_tgt[colBase + t];
    }
    __syncthreads();

    const __nv_bfloat16* gsrc[2] = {
        g_xhi + (size_t)rowBase * D, g_xhi + (size_t)colBase * D
    };
    int r0 = t >> 1, h = t & 1;
    unsigned stoff = tswz(r0, h);

    auto issueStage = [&](int j) {
        unsigned sb = sbase + (unsigned)((j & 1) * STAGE_B);
        size_t kb = (size_t)j * KS;
#pragma unroll
        for (int op = 0; op < 2; op++) {
#pragma unroll
            for (int ks = 0; ks < 4; ks++) {
                unsigned dst = sb + (unsigned)((op * 4 + ks) * TILE_B) + stoff;
                const void* src = gsrc[op] + (size_t)r0 * D + kb + ks * 16 + h * 8;
                cp16(dst, src);
            }
        }
        asm volatile("cp.async.commit_group;" ::: "memory");
    };

    float C[4][4][4];
#pragma unroll
    for (int mi = 0; mi < 4; mi++)
#pragma unroll
        for (int ni = 0; ni < 4; ni++)
#pragma unroll
            for (int q = 0; q < 4; q++) C[mi][ni][q] = 0.f;

    int sub = lid >> 3, lr = lid & 7;
    unsigned offA[4], offB[2];
#pragma unroll
    for (int mi = 0; mi < 4; mi++)
        offA[mi] = tswz(warpRow + mi * 16 + (sub & 1) * 8 + lr, sub >> 1);
#pragma unroll
    for (int ni2 = 0; ni2 < 2; ni2++)
        offB[ni2] = tswz(warpCol + ni2 * 16 + (sub >> 1) * 8 + lr, sub & 1);

    issueStage(0);

    for (int kt = 0; kt < NSTG; kt++) {
        asm volatile("cp.async.wait_group 0;" ::: "memory");
        __syncthreads();          // stage kt loaded; all warps done with kt-1
        if (kt + 1 < NSTG) issueStage(kt + 1);  // safe: reuses buffer of kt-1

        unsigned base = sbase + (unsigned)((kt & 1) * STAGE_B);
#pragma unroll
        for (int ks = 0; ks < 4; ks++) {
            unsigned aT = base + (unsigned)((0 * 4 + ks) * TILE_B);
            unsigned bT = base + (unsigned)((1 * 4 + ks) * TILE_B);
            unsigned ahi[4][4], bh[2][4];
#pragma unroll
            for (int mi = 0; mi < 4; mi++) ldsm4(ahi[mi], aT + offA[mi]);
#pragma unroll
            for (int ni2 = 0; ni2 < 2; ni2++) ldsm4(bh[ni2], bT + offB[ni2]);
#pragma unroll
            for (int mi = 0; mi < 4; mi++)
#pragma unroll
                for (int ni2 = 0; ni2 < 2; ni2++)
#pragma unroll
                    for (int f = 0; f < 2; f++)
                        mma16816(C[mi][ni2 * 2 + f], ahi[mi], bh[ni2][2 * f], bh[ni2][2 * f + 1]);
        }
    }

    // ---- epilogue: top-2 mining on SQUARED distances ----
    // C[mi][ni][rh*2+cb]: row = warpRow + mi*16 + lid/4 + rh*8,
    //                     col = warpCol + ni*8 + (lid%4)*2 + cb
#pragma unroll
    for (int mi = 0; mi < 4; mi++) {
#pragma unroll
        for (int rh = 0; rh < 2; rh++) {
            int lrow = warpRow + mi * 16 + (lid >> 2) + rh * 8;
            float sq = sqR[lrow];
            int tr = tgtR[lrow];
            float pv1 = -1e30f, pv2 = -1e30f; int pi1 = IINF, pi2 = IINF;
            float nv1 =  1e30f, nv2 =  1e30f; int ni1 = IINF, ni2 = IINF;
#pragma unroll
            for (int ni = 0; ni < 4; ni++) {
#pragma unroll
                for (int cb = 0; cb < 2; cb++) {
                    int lcol = warpCol + ni * 8 + (lid & 3) * 2 + cb;
                    float ds = sq + sqC[lcol] - 2.f * C[mi][ni][rh * 2 + cb];
                    int gj = colBase + lcol;
                    if (tr == tgtC[lcol]) {
                        if (!(diag && lrow == lcol)) ins_max(pv1, pi1, pv2, pi2, ds, gj);
                    } else {
                        ins_min(nv1, ni1, nv2, ni2, ds, gj);
                    }
                }
            }
            SHFL_MERGE2(ins_max, pv1, pi1, pv2, pi2, 1);
            SHFL_MERGE2(ins_max, pv1, pi1, pv2, pi2, 2);
            SHFL_MERGE2(ins_min, nv1, ni1, nv2, ni2, 1);
            SHFL_MERGE2(ins_min, nv1, ni1, nv2, ni2, 2);
            if ((lid & 3) == 0) {
                rPV[wx][0][lrow] = pv1; rPI[wx][0][lrow] = pi1;
                rPV[wx][1][lrow] = pv2; rPI[wx][1][lrow] = pi2;
                rNV[wx][0][lrow] = nv1; rNI[wx][0][lrow] = ni1;
                rNV[wx][1][lrow] = nv2; rNI[wx][1][lrow] = ni2;
            }
        }
    }
    __syncthreads();
    if (t < 128) {
        float pv1 = -1e30f, pv2 = -1e30f; int pi1 = IINF, pi2 = IINF;
        float nv1 =  1e30f, nv2 =  1e30f; int ni1 = IINF, ni2 = IINF;
#pragma unroll
        for (int s = 0; s < 4; s++)
#pragma unroll
            for (int e = 0; e < 2; e++) {
                ins_max(pv1, pi1, pv2, pi2, rPV[s][e][t], rPI[s][e][t]);
                ins_min(nv1, ni1, nv2, ni2, rNV[s][e][t], rNI[s][e][t]);
            }
        int r = rowBase + t;
        g_posVal[(bx * 2 + 0) * N + r] = pv1; g_posIdx[(bx * 2 + 0) * N + r] = pi1;
        g_posVal[(bx * 2 + 1) * N + r] = pv2; g_posIdx[(bx * 2 + 1) * N + r] = pi2;
        g_negVal[(bx * 2 + 0) * N + r] = nv1; g_negIdx[(bx * 2 + 0) * N + r] = ni1;
        g_negVal[(bx * 2 + 1) * N + r] = nv2; g_negIdx[(bx * 2 + 1) * N + r] = ni2;
    }

    if (!diag) {
        __syncthreads();
#pragma unroll
        for (int ni = 0; ni < 4; ni++) {
#pragma unroll
            for (int cb = 0; cb < 2; cb++) {
                int lcol = warpCol + ni * 8 + (lid & 3) * 2 + cb;
                float sqc = sqC[lcol];
                int tc = tgtC[lcol];
                float pv1 = -1e30f, pv2 = -1e30f; int pi1 = IINF, pi2 = IINF;
                float nv1 =  1e30f, nv2 =  1e30f; int ni1 = IINF, ni2 = IINF;
#pragma unroll
                for (int mi = 0; mi < 4; mi++) {
#pragma unroll
                    for (int rh = 0; rh < 2; rh++) {
                        int lrow = warpRow + mi * 16 + (lid >> 2) + rh * 8;
                        float ds = sqR[lrow] + sqc - 2.f * C[mi][ni][rh * 2 + cb];
                        int gi = rowBase + lrow;
                        if (tc == tgtR[lrow]) ins_max(pv1, pi1, pv2, pi2, ds, gi);
                        else                  ins_min(nv1, ni1, nv2, ni2, ds, gi);
                    }
                }
                SHFL_MERGE2(ins_max, pv1, pi1, pv2, pi2, 4);
                SHFL_MERGE2(ins_max, pv1, pi1, pv2, pi2, 8);
                SHFL_MERGE2(ins_max, pv1, pi1, pv2, pi2, 16);
                SHFL_MERGE2(ins_min, nv1, ni1, nv2, ni2, 4);
                SHFL_MERGE2(ins_min, nv1, ni1, nv2, ni2, 8);
                SHFL_MERGE2(ins_min, nv1, ni1, nv2, ni2, 16);
                if (lid < 4) {
                    cPV[wy][0][lcol] = pv1; cPI[wy][0][lcol] = pi1;
                    cPV[wy][1][lcol] = pv2; cPI[wy][1][lcol] = pi2;
                    cNV[wy][0][lcol] = nv1; cNI[wy][0][lcol] = ni1;
                    cNV[wy][1][lcol] = nv2; cNI[wy][1][lcol] = ni2;
                }
            }
        }
        __syncthreads();
        if (t < 128) {
            float pv1 = -1e30f, pv2 = -1e30f; int pi1 = IINF, pi2 = IINF;
            float nv1 =  1e30f, nv2 =  1e30f; int ni1 = IINF, ni2 = IINF;
#pragma unroll
            for (int s = 0; s < 2; s++)
#pragma unroll
                for (int e = 0; e < 2; e++) {
                    ins_max(pv1, pi1, pv2, pi2, cPV[s][e][t], cPI[s][e][t]);
                    ins_min(nv1, ni1, nv2, ni2, cNV[s][e][t], cNI[s][e][t]);
                }
            int r = colBase + t;
            g_posVal[(by * 2 + 0) * N + r] = pv1; g_posIdx[(by * 2 + 0) * N + r] = pi1;
            g_posVal[(by * 2 + 1) * N + r] = pv2; g_posIdx[(by * 2 + 1) * N + r] = pi2;
            g_negVal[(by * 2 + 0) * N + r] = nv1; g_negIdx[(by * 2 + 0) * N + r] = ni1;
            g_negVal[(by * 2 + 1) * N + r] = nv2; g_negIdx[(by * 2 + 1) * N + r] = ni2;
        }
    }
}

// ---------------- kernel 3: top-4 select + exact fp32 refine + local --------
__device__ __forceinline__ float warpDot(const float* a, const float* b, int lane) {
    float s = 0.f;
    for (int k = lane * 4; k < D; k += 128) {
        float4 x = *(const float4*)(a + k);
        float4 y = *(const float4*)(b + k);
        s += x.x * y.x + x.y * y.y + x.z * y.z + x.w * y.w;
    }
#pragma unroll
    for (int off = 16; off > 0; off >>= 1)
        s += __shfl_xor_sync(0xffffffffu, s, off);
    return s;
}

__global__ void finalize_rows(const float* __restrict__ X, const float* __restrict__ XL) {
    int warp = (blockIdx.x * blockDim.x + threadIdx.x) >> 5;
    int lane = threadIdx.x & 31;
    if (warp >= N) return;
    int row = warp;

    float pv[2], nvv[2]; int pidx[2], nidx[2];
#pragma unroll
    for (int e = 0; e < 2; e++) {
        pv[e]   = g_posVal[(lane * 2 + e) * N + row];
        pidx[e] = g_posIdx[(lane * 2 + e) * N + row];
        nvv[e]  = g_negVal[(lane * 2 + e) * N + row];
        nidx[e] = g_negIdx[(lane * 2 + e) * N + row];
    }

    int nsel[4];
#pragma unroll
    for (int it = 0; it < 4; it++) {
        float bv = 1e30f; int bi = IINF;
#pragma unroll
        for (int e = 0; e < 2; e++)
            if (nvv[e] < bv || (nvv[e] == bv && nidx[e] < bi)) { bv = nvv[e]; bi = nidx[e]; }
#pragma unroll
        for (int off = 16; off > 0; off >>= 1) {
            float ov = __shfl_xor_sync(0xffffffffu, bv, off);
            int   oi = __shfl_xor_sync(0xffffffffu, bi, off);
            if (ov < bv || (ov == bv && oi < bi)) { bv = ov; bi = oi; }
        }
        nsel[it] = bi;
#pragma unroll
        for (int e = 0; e < 2; e++)
            if (nidx[e] == bi) { nvv[e] = 1e30f; nidx[e] = IINF; }
    }
    int psel[4];
#pragma unroll
    for (int it = 0; it < 4; it++) {
        float bv = -1e30f; int bi = IINF;
#pragma unroll
        for (int e = 0; e < 2; e++)
            if (pv[e] > bv || (pv[e] == bv && pidx[e] < bi)) { bv = pv[e]; bi = pidx[e]; }
#pragma unroll
        for (int off = 16; off > 0; off >>= 1) {
            float ov = __shfl_xor_sync(0xffffffffu, bv, off);
            int   oi = __shfl_xor_sync(0xffffffffu, bi, off);
            if (ov > bv || (ov == bv && oi < bi)) { bv = ov; bi = oi; }
        }
        psel[it] = bi;
#pragma unroll
        for (int e = 0; e < 2; e++)
            if (pidx[e] == bi) { pv[e] = -1e30f; pidx[e] = IINF; }
    }

    const float* xr = X + (size_t)row * D;
    float sqr = g_sq[row];
    float bestPd = -1e30f; int bestPi = IINF;
#pragma unroll
    for (int it = 0; it < 4; it++) {
        int j = psel[it];
        if (j < 0 || j >= N) continue;
        float dot = warpDot(xr, X + (size_t)j * D, lane);
        float d = sqrtf(fmaxf(sqr + g_sq[j] - 2.f * dot, EPSC));
        if (d > bestPd || (d == bestPd && j < bestPi)) { bestPd = d; bestPi = j; }
    }
    float bestNd = 1e30f; int bestNi = IINF;
#pragma unroll
    for (int it = 0; it < 4; it++) {
        int j = nsel[it];
        if (j < 0 || j >= N) continue;
        float dot = warpDot(xr, X + (size_t)j * D, lane);
        float d = sqrtf(fmaxf(sqr + g_sq[j] - 2.f * dot, EPSC));
        if (d < bestNd || (d == bestNd && j < bestNi)) { bestNd = d; bestNi = j; }
    }
    int pi = (bestPi < 0 || bestPi >= N) ? row : bestPi;
    int ni = (bestNi < 0 || bestNi >= N) ? row : bestNi;

    const float* li = XL + (size_t)row * DL;
    const float* lp = XL + (size_t)pi  * DL;
    const float* ln = XL + (size_t)ni  * DL;
    float dp = 0.f, dn = 0.f;
    for (int k = lane * 4; k < DL; k += 128) {
        float4 a = *(const float4*)(li + k);
        float4 b = *(const float4*)(lp + k);
        float4 c = *(const float4*)(ln + k);
        dp += a.x * b.x + a.y * b.y + a.z * b.z + a.w * b.w;
        dn += a.x * c.x + a.y * c.y + a.z * c.z + a.w * c.w;
    }
#pragma unroll
    for (int off = 16; off > 0; off >>= 1) {
        dp += __shfl_xor_sync(0xffffffffu, dp, off);
        dn += __shfl_xor_sync(0xffffffffu, dn, off);
    }
    if (lane == 0) {
        float lap = sqrtf(fmaxf(g_lsq[row] + g_lsq[pi] - 2.f * dp, EPSC));
        float lan = sqrtf(fmaxf(g_lsq[row] + g_lsq[ni] - 2.f * dn, EPSC));
        g_rowLoss[row]  = fmaxf(0.f, bestPd - bestNd + MARGIN);
        g_rowLocal[row] = fmaxf(0.f, lap - lan + MARGIN);
    }
}

// ---------------- kernel 4: deterministic means ----------------
__global__ void final_reduce(float* __restrict__ out, int out_size) {
    __shared__ float s1[256], s2[256];
    int t = threadIdx.x;
    float a = 0.f, b = 0.f;
    for (int i = t; i < N; i += 256) { a += g_rowLoss[i]; b += g_rowLocal[i]; }
    s1[t] = a; s2[t] = b;
    __syncthreads();
    for (int off = 128; off > 0; off >>= 1) {
        if (t < off) { s1[t] += s1[t + off]; s2[t] += s2[t + off]; }
        __syncthreads();
    }
    if (t == 0) {
        out[0] = s1[0] / (float)N;
        if (out_size > 1) out[1] = s2[0] / (float)N;
    }
}

// ---------------- launch ----------------
extern "C" void kernel_launch(void* const* d_in, const int* in_sizes, int n_in,
                              void* d_out, int out_size) {
    const float* X  = (const float*)d_in[0];
    const float* XL = (const float*)d_in[1];
    const int*   T  = (const int*)d_in[2];
    (void)in_sizes; (void)n_in;

    cudaFuncSetAttribute(gram_mma_kernel,
                         cudaFuncAttributeMaxDynamicSharedMemorySize, DYN_B);

    prep_targets<<<1, 1024>>>(T);
    convert_kernel<<<N, 256>>>(X);
    lnorms_kernel<<<N, 256>>>(XL);
    gram_mma_kernel<<<NBLK, 256, DYN_B>>>();
    finalize_rows<<<N / 8, 256>>>(X, XL);
    final_reduce<<<1, 256>>>((float*)d_out, out_size);
}

// round 16
// speedup vs baseline: 1.7462x; 1.2473x over previous
#include <cuda_runtime.h>
#include <cstdint>

#define N    4096
#define D    2048
#define DL   1024
#define BM   128
#define BN   128
#define KS   64                  // int8 k elems per stage (2 k32 slices)
#define NSTG (D / KS)            // 32
#define PIPE 4
#define NTILE (N / BN)           // 32
#define NBLK  (NTILE * (NTILE + 1) / 2)  // 528
#define TILE_I8  (BM * KS)       // 8192 B per operand tile
#define STAGE_B  (2 * TILE_I8)   // 16 KB
#define DYN_B    (PIPE * STAGE_B)  // 64 KB -> 2 blocks/SM with ~28 KB static
#define MARGIN 0.3f
#define EPSC   1e-12f
#define IINF   0x7fffffff

// ---------------- scratch (no allocations allowed) ----------------
__device__ int   g_tgt[N];
__device__ float g_sq[N];
__device__ float g_lsq[N];
__device__ float g_qs[N];                      // per-row quant scale
__device__ signed char g_xq[(size_t)N * D];    // int8 quantized X
__device__ float g_posVal[NTILE * 2 * N];
__device__ int   g_posIdx[NTILE * 2 * N];
__device__ float g_negVal[NTILE * 2 * N];
__device__ int   g_negIdx[NTILE * 2 * N];
__device__ float g_rowLoss[N];
__device__ float g_rowLocal[N];

// ---------------- helpers ----------------
__device__ __forceinline__ unsigned smem_u32(const void* p) {
    unsigned a;
    asm("{ .reg .u64 t; cvta.to.shared.u64 t, %1; cvt.u32.u64 %0, t; }" : "=r"(a) : "l"(p));
    return a;
}
__device__ __forceinline__ void cp16(unsigned dst, const void* src) {
    asm volatile("cp.async.cg.shared.global [%0], [%1], 16;" :: "r"(dst), "l"(src) : "memory");
}
__device__ __forceinline__ void ldsm4(unsigned* r, unsigned addr) {
    asm volatile("ldmatrix.sync.aligned.m8n8.x4.shared.b16 {%0,%1,%2,%3}, [%4];"
        : "=r"(r[0]), "=r"(r[1]), "=r"(r[2]), "=r"(r[3]) : "r"(addr));
}
__device__ __forceinline__ void mma16832s8(int* c, const unsigned* a, unsigned b0, unsigned b1) {
    asm volatile("mma.sync.aligned.m16n8k32.row.col.s32.s8.s8.s32 "
        "{%0,%1,%2,%3}, {%4,%5,%6,%7}, {%8,%9}, {%0,%1,%2,%3};"
        : "+r"(c[0]), "+r"(c[1]), "+r"(c[2]), "+r"(c[3])
        : "r"(a[0]), "r"(a[1]), "r"(a[2]), "r"(a[3]), "r"(b0), "r"(b1));
}
// int8 tile: 128 rows x 64 B; 16B granule c in 0..3; swizzle keeps 8-row
// ldsm phases conflict-free across all 32 banks.
__device__ __forceinline__ unsigned swz8(int r, int c) {
    return (unsigned)(r * 64 + ((c ^ ((r >> 1) & 3)) << 4));
}
// top-2 insert, "smaller is better", tie-break lower index
__device__ __forceinline__ void ins_min(float& v1, int& i1, float& v2, int& i2, float u, int j) {
    if (u < v1 || (u == v1 && j < i1)) { v2 = v1; i2 = i1; v1 = u; i1 = j; }
    else if (u < v2 || (u == v2 && j < i2)) { v2 = u; i2 = j; }
}
// top-2 insert, "larger is better", tie-break lower index
__device__ __forceinline__ void ins_max(float& v1, int& i1, float& v2, int& i2, float u, int j) {
    if (u > v1 || (u == v1 && j < i1)) { v2 = v1; i2 = i1; v1 = u; i1 = j; }
    else if (u > v2 || (u == v2 && j < i2)) { v2 = u; i2 = j; }
}
#define SHFL_MERGE2(INS, v1, i1, v2, i2, off) do { \
    float _ov1 = __shfl_xor_sync(0xffffffffu, v1, off); \
    int   _oi1 = __shfl_xor_sync(0xffffffffu, i1, off); \
    float _ov2 = __shfl_xor_sync(0xffffffffu, v2, off); \
    int   _oi2 = __shfl_xor_sync(0xffffffffu, i2, off); \
    INS(v1, i1, v2, i2, _ov1, _oi1); \
    INS(v1, i1, v2, i2, _ov2, _oi2); \
} while (0)

// ---------------- kernel 0: normalize targets (int32 vs int64 autodetect) ----
__global__ void prep_targets(const int* __restrict__ T32) {
    int f = 0;
    for (int i = threadIdx.x; i < N / 2; i += blockDim.x) f |= T32[2 * i + 1];
    int any = __syncthreads_or(f);
    bool is64 = (any == 0);
    for (int i = threadIdx.x; i < N; i += blockDim.x)
        g_tgt[i] = is64 ? T32[2 * i] : T32[i];
}

// ---------------- kernel 1: per-row int8 quantize + norms -------------------
__global__ void quant_kernel(const float* __restrict__ X) {
    int row = blockIdx.x;
    int t = threadIdx.x;
    const float* src = X + (size_t)row * D;
    float s = 0.f, mx = 0.f;
    for (int k = t * 4; k < D; k += 256 * 4) {
        float4 v = *(const float4*)(src + k);
        s += v.x * v.x + v.y * v.y + v.z * v.z + v.w * v.w;
        mx = fmaxf(mx, fmaxf(fmaxf(fabsf(v.x), fabsf(v.y)), fmaxf(fabsf(v.z), fabsf(v.w))));
    }
    __shared__ float red[256], rmx[256];
    red[t] = s; rmx[t] = mx;
    __syncthreads();
    for (int off = 128; off > 0; off >>= 1) {
        if (t < off) { red[t] += red[t + off]; rmx[t] = fmaxf(rmx[t], rmx[t + off]); }
        __syncthreads();
    }
    float maxabs = rmx[0];
    float inv = (maxabs > 0.f) ? 127.f / maxabs : 0.f;
    for (int k = t * 4; k < D; k += 256 * 4) {
        float4 v = *(const float4*)(src + k);
        int q0 = __float2int_rn(v.x * inv);
        int q1 = __float2int_rn(v.y * inv);
        int q2 = __float2int_rn(v.z * inv);
        int q3 = __float2int_rn(v.w * inv);
        unsigned p = (unsigned)(q0 & 0xff) | ((unsigned)(q1 & 0xff) << 8) |
                     ((unsigned)(q2 & 0xff) << 16) | ((unsigned)(q3 & 0xff) << 24);
        *(unsigned*)(g_xq + (size_t)row * D + k) = p;
    }
    if (t == 0) {
        g_sq[row] = red[0];
        g_qs[row] = (maxabs > 0.f) ? maxabs / 127.f : 0.f;
    }
}

// ---------------- kernel 1b: local-feature row norms ------------------------
__global__ void lnorms_kernel(const float* __restrict__ XL) {
    int b = blockIdx.x;
    int t = threadIdx.x;
    const float* src = XL + (size_t)b * DL;
    float s = 0.f;
    for (int k = t * 4; k < DL; k += 256 * 4) {
        float4 v = *(const float4*)(src + k);
        s += v.x * v.x + v.y * v.y + v.z * v.z + v.w * v.w;
    }
    __shared__ float red[256];
    red[t] = s;
    __syncthreads();
    for (int off = 128; off > 0; off >>= 1) {
        if (t < off) red[t] += red[t + off];
        __syncthreads();
    }
    if (t == 0) g_lsq[b] = red[0];
}

// ---------------- kernel 2: int8 approx Gram + top-2 dual mining ------------
// approx dist^2 = sq_i + sq_j - 2*s_i*s_j*idot. Mining keeps top-2 per
// (row, tile) per direction; exact fp32 refinement in finalize_rows.
__global__ __launch_bounds__(256, 2)
void gram_mma_kernel() {
    int kblk = blockIdx.x;
    int bx = (int)((sqrtf(8.0f * (float)kblk + 1.0f) - 1.0f) * 0.5f);
    while (bx * (bx + 1) / 2 > kblk) bx--;
    while ((bx + 1) * (bx + 2) / 2 <= kblk) bx++;
    int by = kblk - bx * (bx + 1) / 2;
    int rowBase = by * BM, colBase = bx * BN;
    bool diag = (bx == by);

    extern __shared__ __align__(16) char dyn[];
    __shared__ float sqR[BM], sqC[BN], scR[BM], scC[BN];
    __shared__ int   tgtR[BM], tgtC[BN];
    __shared__ float rPV[4][2][128], rNV[4][2][128];
    __shared__ int   rPI[4][2][128], rNI[4][2][128];
    __shared__ float cPV[2][2][128], cNV[2][2][128];
    __shared__ int   cPI[2][2][128], cNI[2][2][128];

    int t = threadIdx.x, wid = t >> 5, lid = t & 31;
    int wy = wid >> 2, wx = wid & 3;           // 2 x 4 warp grid
    int warpRow = wy * 64, warpCol = wx * 32;  // warp tile 64 x 32
    unsigned sbase = smem_u32(dyn);

    if (t < 128) {
        sqR[t] = g_sq[rowBase + t]; scR[t] = g_qs[rowBase + t]; tgtR[t] = g_tgt[rowBase + t];
        sqC[t] = g_sq[colBase + t]; scC[t] = g_qs[colBase + t]; tgtC[t] = g_tgt[colBase + t];
    }
    __syncthreads();

    const signed char* gsrc[2] = {
        g_xq + (size_t)rowBase * D, g_xq + (size_t)colBase * D
    };
    // staging: thread t -> row r0 = t>>1, two 16B granules cp, cp+1
    int r0 = t >> 1, cp = (t & 1) * 2;
    unsigned po0 = swz8(r0, cp + 0);
    unsigned po1 = swz8(r0, cp + 1);

    auto issueStage = [&](int j) {
        unsigned sb = sbase + (unsigned)((j & 3) * STAGE_B);
#pragma unroll
        for (int op = 0; op < 2; op++) {
            unsigned db = sb + (unsigned)(op * TILE_I8);
            const signed char* src = gsrc[op] + (size_t)r0 * D + j * KS + cp * 16;
            cp16(db + po0, src);
            cp16(db + po1, src + 16);
        }
        asm volatile("cp.async.commit_group;" ::: "memory");
    };

    int C[4][4][4];
#pragma unroll
    for (int mi = 0; mi < 4; mi++)
#pragma unroll
        for (int ni = 0; ni < 4; ni++)
#pragma unroll
            for (int q = 0; q < 4; q++) C[mi][ni][q] = 0;

    // ldsm offsets: A per (slice s, mi); B per (s, nj2)
    int sub = lid >> 3, lr = lid & 7;
    unsigned offA[2][4], offB[2][2];
#pragma unroll
    for (int s = 0; s < 2; s++) {
#pragma unroll
        for (int mi = 0; mi < 4; mi++) {
            int r = warpRow + mi * 16 + lr + (sub & 1) * 8;
            offA[s][mi] = swz8(r, 2 * s + (sub >> 1));
        }
#pragma unroll
        for (int nj2 = 0; nj2 < 2; nj2++) {
            int r = warpCol + nj2 * 16 + lr + (sub >> 1) * 8;
            offB[s][nj2] = swz8(r, 2 * s + (sub & 1));
        }
    }

    issueStage(0);
    issueStage(1);
    issueStage(2);

    for (int kt = 0; kt < NSTG; kt++) {
        if (kt <= NSTG - 3) {
            asm volatile("cp.async.wait_group 2;" ::: "memory");
        } else if (kt == NSTG - 2) {
            asm volatile("cp.async.wait_group 1;" ::: "memory");
        } else {
            asm volatile("cp.async.wait_group 0;" ::: "memory");
        }
        __syncthreads();
        if (kt + 3 < NSTG) issueStage(kt + 3);

        unsigned base = sbase + (unsigned)((kt & 3) * STAGE_B);
        unsigned aT = base, bT = base + TILE_I8;
#pragma unroll
        for (int s = 0; s < 2; s++) {
            unsigned a[4][4], b[2][4];
#pragma unroll
            for (int mi = 0; mi < 4; mi++) ldsm4(a[mi], aT + offA[s][mi]);
#pragma unroll
            for (int nj2 = 0; nj2 < 2; nj2++) ldsm4(b[nj2], bT + offB[s][nj2]);
#pragma unroll
            for (int mi = 0; mi < 4; mi++)
#pragma unroll
                for (int nj2 = 0; nj2 < 2; nj2++)
#pragma unroll
                    for (int f = 0; f < 2; f++)
                        mma16832s8(C[mi][nj2 * 2 + f], a[mi], b[nj2][2 * f], b[nj2][2 * f + 1]);
        }
    }

    // ---- epilogue: top-2 mining on approx squared distances ----
    // C[mi][ni][rh*2+cb]: row = warpRow + mi*16 + lid/4 + rh*8,
    //                     col = warpCol + ni*8 + (lid%4)*2 + cb
#pragma unroll
    for (int mi = 0; mi < 4; mi++) {
#pragma unroll
        for (int rh = 0; rh < 2; rh++) {
            int lrow = warpRow + mi * 16 + (lid >> 2) + rh * 8;
            float sq = sqR[lrow];
            float sr2 = 2.f * scR[lrow];
            int tr = tgtR[lrow];
            float pv1 = -1e30f, pv2 = -1e30f; int pi1 = IINF, pi2 = IINF;
            float nv1 =  1e30f, nv2 =  1e30f; int ni1 = IINF, ni2 = IINF;
#pragma unroll
            for (int ni = 0; ni < 4; ni++) {
#pragma unroll
                for (int cb = 0; cb < 2; cb++) {
                    int lcol = warpCol + ni * 8 + (lid & 3) * 2 + cb;
                    float ds = sq + sqC[lcol] - sr2 * scC[lcol] * (float)C[mi][ni][rh * 2 + cb];
                    int gj = colBase + lcol;
                    if (tr == tgtC[lcol]) {
                        if (!(diag && lrow == lcol)) ins_max(pv1, pi1, pv2, pi2, ds, gj);
                    } else {
                        ins_min(nv1, ni1, nv2, ni2, ds, gj);
                    }
                }
            }
            SHFL_MERGE2(ins_max, pv1, pi1, pv2, pi2, 1);
            SHFL_MERGE2(ins_max, pv1, pi1, pv2, pi2, 2);
            SHFL_MERGE2(ins_min, nv1, ni1, nv2, ni2, 1);
            SHFL_MERGE2(ins_min, nv1, ni1, nv2, ni2, 2);
            if ((lid & 3) == 0) {
                rPV[wx][0][lrow] = pv1; rPI[wx][0][lrow] = pi1;
                rPV[wx][1][lrow] = pv2; rPI[wx][1][lrow] = pi2;
                rNV[wx][0][lrow] = nv1; rNI[wx][0][lrow] = ni1;
                rNV[wx][1][lrow] = nv2; rNI[wx][1][lrow] = ni2;
            }
        }
    }
    __syncthreads();
    if (t < 128) {
        float pv1 = -1e30f, pv2 = -1e30f; int pi1 = IINF, pi2 = IINF;
        float nv1 =  1e30f, nv2 =  1e30f; int ni1 = IINF, ni2 = IINF;
#pragma unroll
        for (int s = 0; s < 4; s++)
#pragma unroll
            for (int e = 0; e < 2; e++) {
                ins_max(pv1, pi1, pv2, pi2, rPV[s][e][t], rPI[s][e][t]);
                ins_min(nv1, ni1, nv2, ni2, rNV[s][e][t], rNI[s][e][t]);
            }
        int r = rowBase + t;
        g_posVal[(bx * 2 + 0) * N + r] = pv1; g_posIdx[(bx * 2 + 0) * N + r] = pi1;
        g_posVal[(bx * 2 + 1) * N + r] = pv2; g_posIdx[(bx * 2 + 1) * N + r] = pi2;
        g_negVal[(bx * 2 + 0) * N + r] = nv1; g_negIdx[(bx * 2 + 0) * N + r] = ni1;
        g_negVal[(bx * 2 + 1) * N + r] = nv2; g_negIdx[(bx * 2 + 1) * N + r] = ni2;
    }

    if (!diag) {
        __syncthreads();
#pragma unroll
        for (int ni = 0; ni < 4; ni++) {
#pragma unroll
            for (int cb = 0; cb < 2; cb++) {
                int lcol = warpCol + ni * 8 + (lid & 3) * 2 + cb;
                float sqc = sqC[lcol];
                float sc2 = 2.f * scC[lcol];
                int tc = tgtC[lcol];
                float pv1 = -1e30f, pv2 = -1e30f; int pi1 = IINF, pi2 = IINF;
                float nv1 =  1e30f, nv2 =  1e30f; int ni1 = IINF, ni2 = IINF;
#pragma unroll
                for (int mi = 0; mi < 4; mi++) {
#pragma unroll
                    for (int rh = 0; rh < 2; rh++) {
                        int lrow = warpRow + mi * 16 + (lid >> 2) + rh * 8;
                        float ds = sqR[lrow] + sqc - sc2 * scR[lrow] * (float)C[mi][ni][rh * 2 + cb];
                        int gi = rowBase + lrow;
                        if (tc == tgtR[lrow]) ins_max(pv1, pi1, pv2, pi2, ds, gi);
                        else                  ins_min(nv1, ni1, nv2, ni2, ds, gi);
                    }
                }
                SHFL_MERGE2(ins_max, pv1, pi1, pv2, pi2, 4);
                SHFL_MERGE2(ins_max, pv1, pi1, pv2, pi2, 8);
                SHFL_MERGE2(ins_max, pv1, pi1, pv2, pi2, 16);
                SHFL_MERGE2(ins_min, nv1, ni1, nv2, ni2, 4);
                SHFL_MERGE2(ins_min, nv1, ni1, nv2, ni2, 8);
                SHFL_MERGE2(ins_min, nv1, ni1, nv2, ni2, 16);
                if (lid < 4) {
                    cPV[wy][0][lcol] = pv1; cPI[wy][0][lcol] = pi1;
                    cPV[wy][1][lcol] = pv2; cPI[wy][1][lcol] = pi2;
                    cNV[wy][0][lcol] = nv1; cNI[wy][0][lcol] = ni1;
                    cNV[wy][1][lcol] = nv2; cNI[wy][1][lcol] = ni2;
                }
            }
        }
        __syncthreads();
        if (t < 128) {
            float pv1 = -1e30f, pv2 = -1e30f; int pi1 = IINF, pi2 = IINF;
            float nv1 =  1e30f, nv2 =  1e30f; int ni1 = IINF, ni2 = IINF;
#pragma unroll
            for (int s = 0; s < 2; s++)
#pragma unroll
                for (int e = 0; e < 2; e++) {
                    ins_max(pv1, pi1, pv2, pi2, cPV[s][e][t], cPI[s][e][t]);
                    ins_min(nv1, ni1, nv2, ni2, cNV[s][e][t], cNI[s][e][t]);
                }
            int r = colBase + t;
            g_posVal[(by * 2 + 0) * N + r] = pv1; g_posIdx[(by * 2 + 0) * N + r] = pi1;
            g_posVal[(by * 2 + 1) * N + r] = pv2; g_posIdx[(by * 2 + 1) * N + r] = pi2;
            g_negVal[(by * 2 + 0) * N + r] = nv1; g_negIdx[(by * 2 + 0) * N + r] = ni1;
            g_negVal[(by * 2 + 1) * N + r] = nv2; g_negIdx[(by * 2 + 1) * N + r] = ni2;
        }
    }
}

// ---------------- kernel 3: top-4 select + exact fp32 refine + local --------
__device__ __forceinline__ float warpDot(const float* a, const float* b, int lane) {
    float s = 0.f;
    for (int k = lane * 4; k < D; k += 128) {
        float4 x = *(const float4*)(a + k);
        float4 y = *(const float4*)(b + k);
        s += x.x * y.x + x.y * y.y + x.z * y.z + x.w * y.w;
    }
#pragma unroll
    for (int off = 16; off > 0; off >>= 1)
        s += __shfl_xor_sync(0xffffffffu, s, off);
    return s;
}

__global__ void finalize_rows(const float* __restrict__ X, const float* __restrict__ XL) {
    int warp = (blockIdx.x * blockDim.x + threadIdx.x) >> 5;
    int lane = threadIdx.x & 31;
    if (warp >= N) return;
    int row = warp;

    float pv[2], nvv[2]; int pidx[2], nidx[2];
#pragma unroll
    for (int e = 0; e < 2; e++) {
        pv[e]   = g_posVal[(lane * 2 + e) * N + row];
        pidx[e] = g_posIdx[(lane * 2 + e) * N + row];
        nvv[e]  = g_negVal[(lane * 2 + e) * N + row];
        nidx[e] = g_negIdx[(lane * 2 + e) * N + row];
    }

    int nsel[4];
#pragma unroll
    for (int it = 0; it < 4; it++) {
        float bv = 1e30f; int bi = IINF;
#pragma unroll
        for (int e = 0; e < 2; e++)
            if (nvv[e] < bv || (nvv[e] == bv && nidx[e] < bi)) { bv = nvv[e]; bi = nidx[e]; }
#pragma unroll
        for (int off = 16; off > 0; off >>= 1) {
            float ov = __shfl_xor_sync(0xffffffffu, bv, off);
            int   oi = __shfl_xor_sync(0xffffffffu, bi, off);
            if (ov < bv || (ov == bv && oi < bi)) { bv = ov; bi = oi; }
        }
        nsel[it] = bi;
#pragma unroll
        for (int e = 0; e < 2; e++)
            if (nidx[e] == bi) { nvv[e] = 1e30f; nidx[e] = IINF; }
    }
    int psel[4];
#pragma unroll
    for (int it = 0; it < 4; it++) {
        float bv = -1e30f; int bi = IINF;
#pragma unroll
        for (int e = 0; e < 2; e++)
            if (pv[e] > bv || (pv[e] == bv && pidx[e] < bi)) { bv = pv[e]; bi = pidx[e]; }
#pragma unroll
        for (int off = 16; off > 0; off >>= 1) {
            float ov = __shfl_xor_sync(0xffffffffu, bv, off);
            int   oi = __shfl_xor_sync(0xffffffffu, bi, off);
            if (ov > bv || (ov == bv && oi < bi)) { bv = ov; bi = oi; }
        }
        psel[it] = bi;
#pragma unroll
        for (int e = 0; e < 2; e++)
            if (pidx[e] == bi) { pv[e] = -1e30f; pidx[e] = IINF; }
    }

    const float* xr = X + (size_t)row * D;
    float sqr = g_sq[row];
    float bestPd = -1e30f; int bestPi = IINF;
#pragma unroll
    for (int it = 0; it < 4; it++) {
        int j = psel[it];
        if (j < 0 || j >= N) continue;
        float dot = warpDot(xr, X + (size_t)j * D, lane);
        float d = sqrtf(fmaxf(sqr + g_sq[j] - 2.f * dot, EPSC));
        if (d > bestPd || (d == bestPd && j < bestPi)) { bestPd = d; bestPi = j; }
    }
    float bestNd = 1e30f; int bestNi = IINF;
#pragma unroll
    for (int it = 0; it < 4; it++) {
        int j = nsel[it];
        if (j < 0 || j >= N) continue;
        float dot = warpDot(xr, X + (size_t)j * D, lane);
        float d = sqrtf(fmaxf(sqr + g_sq[j] - 2.f * dot, EPSC));
        if (d < bestNd || (d == bestNd && j < bestNi)) { bestNd = d; bestNi = j; }
    }
    int pi = (bestPi < 0 || bestPi >= N) ? row : bestPi;
    int ni = (bestNi < 0 || bestNi >= N) ? row : bestNi;

    const float* li = XL + (size_t)row * DL;
    const float* lp = XL + (size_t)pi  * DL;
    const float* ln = XL + (size_t)ni  * DL;
    float dp = 0.f, dn = 0.f;
    for (int k = lane * 4; k < DL; k += 128) {
        float4 a = *(const float4*)(li + k);
        float4 b = *(const float4*)(lp + k);
        float4 c = *(const float4*)(ln + k);
        dp += a.x * b.x + a.y * b.y + a.z * b.z + a.w * b.w;
        dn += a.x * c.x + a.y * c.y + a.z * c.z + a.w * c.w;
    }
#pragma unroll
    for (int off = 16; off > 0; off >>= 1) {
        dp += __shfl_xor_sync(0xffffffffu, dp, off);
        dn += __shfl_xor_sync(0xffffffffu, dn, off);
    }
    if (lane == 0) {
        float lap = sqrtf(fmaxf(g_lsq[row] + g_lsq[pi] - 2.f * dp, EPSC));
        float lan = sqrtf(fmaxf(g_lsq[row] + g_lsq[ni] - 2.f * dn, EPSC));
        g_rowLoss[row]  = fmaxf(0.f, bestPd - bestNd + MARGIN);
        g_rowLocal[row] = fmaxf(0.f, lap - lan + MARGIN);
    }
}

// ---------------- kernel 4: deterministic means ----------------
__global__ void final_reduce(float* __restrict__ out, int out_size) {
    __shared__ float s1[256], s2[256];
    int t = threadIdx.x;
    float a = 0.f, b = 0.f;
    for (int i = t; i < N; i += 256) { a += g_rowLoss[i]; b += g_rowLocal[i]; }
    s1[t] = a; s2[t] = b;
    __syncthreads();
    for (int off = 128; off > 0; off >>= 1) {
        if (t < off) { s1[t] += s1[t + off]; s2[t] += s2[t + off]; }
        __syncthreads();
    }
    if (t == 0) {
        out[0] = s1[0] / (float)N;
        if (out_size > 1) out[1] = s2[0] / (float)N;
    }
}

// ---------------- launch ----------------
extern "C" void kernel_launch(void* const* d_in, const int* in_sizes, int n_in,
                              void* d_out, int out_size) {
    const float* X  = (const float*)d_in[0];
    const float* XL = (const float*)d_in[1];
    const int*   T  = (const int*)d_in[2];
    (void)in_sizes; (void)n_in;

    cudaFuncSetAttribute(gram_mma_kernel,
                         cudaFuncAttributeMaxDynamicSharedMemorySize, DYN_B);

    prep_targets<<<1, 1024>>>(T);
    quant_kernel<<<N, 256>>>(X);
    lnorms_kernel<<<N, 256>>>(XL);
    gram_mma_kernel<<<NBLK, 256, DYN_B>>>();
    finalize_rows<<<N / 8, 256>>>(X, XL);
    final_reduce<<<1, 256>>>((float*)d_out, out_size);
}

// round 17
// speedup vs baseline: 1.7667x; 1.0117x over previous
#include <cuda_runtime.h>
#include <cstdint>

#define N    4096
#define D    2048
#define DL   1024
#define BM   128
#define BN   128
#define KS   128                 // int8 k elems per stage (4 k32 slices)
#define NSTG (D / KS)            // 16
#define NTILE (N / BN)           // 32
#define NBLK  (NTILE * (NTILE + 1) / 2)  // 528
#define TILE_I8  (BM * KS)       // 16384 B per operand tile
#define STAGE_B  (2 * TILE_I8)   // 32 KB
#define DYN_B    (2 * STAGE_B)   // 64 KB double buffer -> 2 blocks/SM
#define MARGIN 0.3f
#define EPSC   1e-12f
#define IINF   0x7fffffff

// ---------------- scratch (no allocations allowed) ----------------
__device__ int   g_tgt[N];
__device__ float g_sq[N];
__device__ float g_lsq[N];
__device__ float g_qs[N];                      // per-row quant scale
__device__ signed char g_xq[(size_t)N * D];    // int8 quantized X
__device__ float g_posVal[NTILE * 2 * N];
__device__ int   g_posIdx[NTILE * 2 * N];
__device__ float g_negVal[NTILE * 2 * N];
__device__ int   g_negIdx[NTILE * 2 * N];
__device__ float g_rowLoss[N];
__device__ float g_rowLocal[N];

// ---------------- helpers ----------------
__device__ __forceinline__ unsigned smem_u32(const void* p) {
    unsigned a;
    asm("{ .reg .u64 t; cvta.to.shared.u64 t, %1; cvt.u32.u64 %0, t; }" : "=r"(a) : "l"(p));
    return a;
}
__device__ __forceinline__ void cp16(unsigned dst, const void* src) {
    asm volatile("cp.async.cg.shared.global [%0], [%1], 16;" :: "r"(dst), "l"(src) : "memory");
}
__device__ __forceinline__ void ldsm4(unsigned* r, unsigned addr) {
    asm volatile("ldmatrix.sync.aligned.m8n8.x4.shared.b16 {%0,%1,%2,%3}, [%4];"
        : "=r"(r[0]), "=r"(r[1]), "=r"(r[2]), "=r"(r[3]) : "r"(addr));
}
__device__ __forceinline__ void mma16832s8(int* c, const unsigned* a, unsigned b0, unsigned b1) {
    asm volatile("mma.sync.aligned.m16n8k32.row.col.s32.s8.s8.s32 "
        "{%0,%1,%2,%3}, {%4,%5,%6,%7}, {%8,%9}, {%0,%1,%2,%3};"
        : "+r"(c[0]), "+r"(c[1]), "+r"(c[2]), "+r"(c[3])
        : "r"(a[0]), "r"(a[1]), "r"(a[2]), "r"(a[3]), "r"(b0), "r"(b1));
}
// int8 tile: 128 rows x 128 B; 16B granule c in 0..7; XOR with (r&7) makes
// each 8-row ldsm phase hit 8 distinct bank groups -> conflict-free.
__device__ __forceinline__ unsigned swz8(int r, int c) {
    return (unsigned)(r * 128 + ((c ^ (r & 7)) << 4));
}
// top-2 insert, "smaller is better", tie-break lower index
__device__ __forceinline__ void ins_min(float& v1, int& i1, float& v2, int& i2, float u, int j) {
    if (u < v1 || (u == v1 && j < i1)) { v2 = v1; i2 = i1; v1 = u; i1 = j; }
    else if (u < v2 || (u == v2 && j < i2)) { v2 = u; i2 = j; }
}
// top-2 insert, "larger is better", tie-break lower index
__device__ __forceinline__ void ins_max(float& v1, int& i1, float& v2, int& i2, float u, int j) {
    if (u > v1 || (u == v1 && j < i1)) { v2 = v1; i2 = i1; v1 = u; i1 = j; }
    else if (u > v2 || (u == v2 && j < i2)) { v2 = u; i2 = j; }
}
#define SHFL_MERGE2(INS, v1, i1, v2, i2, off) do { \
    float _ov1 = __shfl_xor_sync(0xffffffffu, v1, off); \
    int   _oi1 = __shfl_xor_sync(0xffffffffu, i1, off); \
    float _ov2 = __shfl_xor_sync(0xffffffffu, v2, off); \
    int   _oi2 = __shfl_xor_sync(0xffffffffu, i2, off); \
    INS(v1, i1, v2, i2, _ov1, _oi1); \
    INS(v1, i1, v2, i2, _ov2, _oi2); \
} while (0)

// ---------------- kernel 0: normalize targets (int32 vs int64 autodetect) ----
__global__ void prep_targets(const int* __restrict__ T32) {
    int f = 0;
    for (int i = threadIdx.x; i < N / 2; i += blockDim.x) f |= T32[2 * i + 1];
    int any = __syncthreads_or(f);
    bool is64 = (any == 0);
    for (int i = threadIdx.x; i < N; i += blockDim.x)
        g_tgt[i] = is64 ? T32[2 * i] : T32[i];
}

// ---------------- kernel 1: quantize X + norms; XL norms (merged) -----------
__global__ void quant_kernel(const float* __restrict__ X, const float* __restrict__ XL) {
    int b = blockIdx.x;
    int t = threadIdx.x;
    __shared__ float red[256], rmx[256];
    if (b < N) {
        int row = b;
        const float* src = X + (size_t)row * D;
        float s = 0.f, mx = 0.f;
        for (int k = t * 4; k < D; k += 256 * 4) {
            float4 v = *(const float4*)(src + k);
            s += v.x * v.x + v.y * v.y + v.z * v.z + v.w * v.w;
            mx = fmaxf(mx, fmaxf(fmaxf(fabsf(v.x), fabsf(v.y)), fmaxf(fabsf(v.z), fabsf(v.w))));
        }
        red[t] = s; rmx[t] = mx;
        __syncthreads();
        for (int off = 128; off > 0; off >>= 1) {
            if (t < off) { red[t] += red[t + off]; rmx[t] = fmaxf(rmx[t], rmx[t + off]); }
            __syncthreads();
        }
        float maxabs = rmx[0];
        float inv = (maxabs > 0.f) ? 127.f / maxabs : 0.f;
        for (int k = t * 4; k < D; k += 256 * 4) {
            float4 v = *(const float4*)(src + k);
            int q0 = __float2int_rn(v.x * inv);
            int q1 = __float2int_rn(v.y * inv);
            int q2 = __float2int_rn(v.z * inv);
            int q3 = __float2int_rn(v.w * inv);
            unsigned p = (unsigned)(q0 & 0xff) | ((unsigned)(q1 & 0xff) << 8) |
                         ((unsigned)(q2 & 0xff) << 16) | ((unsigned)(q3 & 0xff) << 24);
            *(unsigned*)(g_xq + (size_t)row * D + k) = p;
        }
        if (t == 0) {
            g_sq[row] = red[0];
            g_qs[row] = (maxabs > 0.f) ? maxabs / 127.f : 0.f;
        }
    } else {
        int row = b - N;
        const float* src = XL + (size_t)row * DL;
        float s = 0.f;
        for (int k = t * 4; k < DL; k += 256 * 4) {
            float4 v = *(const float4*)(src + k);
            s += v.x * v.x + v.y * v.y + v.z * v.z + v.w * v.w;
        }
        red[t] = s;
        __syncthreads();
        for (int off = 128; off > 0; off >>= 1) {
            if (t < off) red[t] += red[t + off];
            __syncthreads();
        }
        if (t == 0) g_lsq[row] = red[0];
    }
}

// ---------------- kernel 2: int8 approx Gram + top-2 dual mining ------------
// approx dist^2 = sq_i + sq_j - 2*s_i*s_j*idot. Mining keeps top-2 per
// (row, tile) per direction; exact fp32 refinement in finalize_rows.
// KS=128 double-buffered: 16 barriers/tile at 2 blocks/SM.
__global__ __launch_bounds__(256, 2)
void gram_mma_kernel() {
    int kblk = blockIdx.x;
    int bx = (int)((sqrtf(8.0f * (float)kblk + 1.0f) - 1.0f) * 0.5f);
    while (bx * (bx + 1) / 2 > kblk) bx--;
    while ((bx + 1) * (bx + 2) / 2 <= kblk) bx++;
    int by = kblk - bx * (bx + 1) / 2;
    int rowBase = by * BM, colBase = bx * BN;
    bool diag = (bx == by);

    extern __shared__ __align__(16) char dyn[];
    __shared__ float sqR[BM], sqC[BN], scR[BM], scC[BN];
    __shared__ int   tgtR[BM], tgtC[BN];
    __shared__ float rPV[4][2][128], rNV[4][2][128];
    __shared__ int   rPI[4][2][128], rNI[4][2][128];
    __shared__ float cPV[2][2][128], cNV[2][2][128];
    __shared__ int   cPI[2][2][128], cNI[2][2][128];

    int t = threadIdx.x, wid = t >> 5, lid = t & 31;
    int wy = wid >> 2, wx = wid & 3;           // 2 x 4 warp grid
    int warpRow = wy * 64, warpCol = wx * 32;  // warp tile 64 x 32
    unsigned sbase = smem_u32(dyn);

    if (t < 128) {
        sqR[t] = g_sq[rowBase + t]; scR[t] = g_qs[rowBase + t]; tgtR[t] = g_tgt[rowBase + t];
        sqC[t] = g_sq[colBase + t]; scC[t] = g_qs[colBase + t]; tgtC[t] = g_tgt[colBase + t];
    }
    __syncthreads();

    const signed char* gsrc[2] = {
        g_xq + (size_t)rowBase * D, g_xq + (size_t)colBase * D
    };
    // staging: thread t -> row r0 = t>>1, four 16B granules cp..cp+3
    int r0 = t >> 1, cp = (t & 1) * 4;
    unsigned po[4];
#pragma unroll
    for (int i = 0; i < 4; i++) po[i] = swz8(r0, cp + i);

    auto issueStage = [&](int j) {
        unsigned sb = sbase + (unsigned)((j & 1) * STAGE_B);
#pragma unroll
        for (int op = 0; op < 2; op++) {
            unsigned db = sb + (unsigned)(op * TILE_I8);
            const signed char* src = gsrc[op] + (size_t)r0 * D + j * KS + cp * 16;
#pragma unroll
            for (int i = 0; i < 4; i++) cp16(db + po[i], src + i * 16);
        }
        asm volatile("cp.async.commit_group;" ::: "memory");
    };

    int C[4][4][4];
#pragma unroll
    for (int mi = 0; mi < 4; mi++)
#pragma unroll
        for (int ni = 0; ni < 4; ni++)
#pragma unroll
            for (int q = 0; q < 4; q++) C[mi][ni][q] = 0;

    // ldsm offsets: A per (slice s, mi); B per (s, nj2); granule encodes k32 slice
    int sub = lid >> 3, lr = lid & 7;
    unsigned offA[4][4], offB[4][2];
#pragma unroll
    for (int s = 0; s < 4; s++) {
#pragma unroll
        for (int mi = 0; mi < 4; mi++) {
            int r = warpRow + mi * 16 + lr + (sub & 1) * 8;
            offA[s][mi] = swz8(r, 2 * s + (sub >> 1));
        }
#pragma unroll
        for (int nj2 = 0; nj2 < 2; nj2++) {
            int r = warpCol + nj2 * 16 + lr + (sub >> 1) * 8;
            offB[s][nj2] = swz8(r, 2 * s + (sub & 1));
        }
    }

    issueStage(0);

    for (int kt = 0; kt < NSTG; kt++) {
        asm volatile("cp.async.wait_group 0;" ::: "memory");
        __syncthreads();          // stage kt loaded; all warps done with kt-1
        if (kt + 1 < NSTG) issueStage(kt + 1);  // reuses buffer of kt-1 (safe)

        unsigned base = sbase + (unsigned)((kt & 1) * STAGE_B);
        unsigned aT = base, bT = base + TILE_I8;
#pragma unroll
        for (int s = 0; s < 4; s++) {
            unsigned a[4][4], b[2][4];
#pragma unroll
            for (int mi = 0; mi < 4; mi++) ldsm4(a[mi], aT + offA[s][mi]);
#pragma unroll
            for (int nj2 = 0; nj2 < 2; nj2++) ldsm4(b[nj2], bT + offB[s][nj2]);
#pragma unroll
            for (int mi = 0; mi < 4; mi++)
#pragma unroll
                for (int nj2 = 0; nj2 < 2; nj2++)
#pragma unroll
                    for (int f = 0; f < 2; f++)
                        mma16832s8(C[mi][nj2 * 2 + f], a[mi], b[nj2][2 * f], b[nj2][2 * f + 1]);
        }
    }

    // ---- epilogue: top-2 mining on approx squared distances ----
    // C[mi][ni][rh*2+cb]: row = warpRow + mi*16 + lid/4 + rh*8,
    //                     col = warpCol + ni*8 + (lid%4)*2 + cb
#pragma unroll
    for (int mi = 0; mi < 4; mi++) {
#pragma unroll
        for (int rh = 0; rh < 2; rh++) {
            int lrow = warpRow + mi * 16 + (lid >> 2) + rh * 8;
            float sq = sqR[lrow];
            float sr2 = 2.f * scR[lrow];
            int tr = tgtR[lrow];
            float pv1 = -1e30f, pv2 = -1e30f; int pi1 = IINF, pi2 = IINF;
            float nv1 =  1e30f, nv2 =  1e30f; int ni1 = IINF, ni2 = IINF;
#pragma unroll
            for (int ni = 0; ni < 4; ni++) {
#pragma unroll
                for (int cb = 0; cb < 2; cb++) {
                    int lcol = warpCol + ni * 8 + (lid & 3) * 2 + cb;
                    float ds = sq + sqC[lcol] - sr2 * scC[lcol] * (float)C[mi][ni][rh * 2 + cb];
                    int gj = colBase + lcol;
                    if (tr == tgtC[lcol]) {
                        if (!(diag && lrow == lcol)) ins_max(pv1, pi1, pv2, pi2, ds, gj);
                    } else {
                        ins_min(nv1, ni1, nv2, ni2, ds, gj);
                    }
                }
            }
            SHFL_MERGE2(ins_max, pv1, pi1, pv2, pi2, 1);
            SHFL_MERGE2(ins_max, pv1, pi1, pv2, pi2, 2);
            SHFL_MERGE2(ins_min, nv1, ni1, nv2, ni2, 1);
            SHFL_MERGE2(ins_min, nv1, ni1, nv2, ni2, 2);
            if ((lid & 3) == 0) {
                rPV[wx][0][lrow] = pv1; rPI[wx][0][lrow] = pi1;
                rPV[wx][1][lrow] = pv2; rPI[wx][1][lrow] = pi2;
                rNV[wx][0][lrow] = nv1; rNI[wx][0][lrow] = ni1;
                rNV[wx][1][lrow] = nv2; rNI[wx][1][lrow] = ni2;
            }
        }
    }
    __syncthreads();
    if (t < 128) {
        float pv1 = -1e30f, pv2 = -1e30f; int pi1 = IINF, pi2 = IINF;
        float nv1 =  1e30f, nv2 =  1e30f; int ni1 = IINF, ni2 = IINF;
#pragma unroll
        for (int s = 0; s < 4; s++)
#pragma unroll
            for (int e = 0; e < 2; e++) {
                ins_max(pv1, pi1, pv2, pi2, rPV[s][e][t], rPI[s][e][t]);
                ins_min(nv1, ni1, nv2, ni2, rNV[s][e][t], rNI[s][e][t]);
            }
        int r = rowBase + t;
        g_posVal[(bx * 2 + 0) * N + r] = pv1; g_posIdx[(bx * 2 + 0) * N + r] = pi1;
        g_posVal[(bx * 2 + 1) * N + r] = pv2; g_posIdx[(bx * 2 + 1) * N + r] = pi2;
        g_negVal[(bx * 2 + 0) * N + r] = nv1; g_negIdx[(bx * 2 + 0) * N + r] = ni1;
        g_negVal[(bx * 2 + 1) * N + r] = nv2; g_negIdx[(bx * 2 + 1) * N + r] = ni2;
    }

    if (!diag) {
        __syncthreads();
#pragma unroll
        for (int ni = 0; ni < 4; ni++) {
#pragma unroll
            for (int cb = 0; cb < 2; cb++) {
                int lcol = warpCol + ni * 8 + (lid & 3) * 2 + cb;
                float sqc = sqC[lcol];
                float sc2 = 2.f * scC[lcol];
                int tc = tgtC[lcol];
                float pv1 = -1e30f, pv2 = -1e30f; int pi1 = IINF, pi2 = IINF;
                float nv1 =  1e30f, nv2 =  1e30f; int ni1 = IINF, ni2 = IINF;
#pragma unroll
                for (int mi = 0; mi < 4; mi++) {
#pragma unroll
                    for (int rh = 0; rh < 2; rh++) {
                        int lrow = warpRow + mi * 16 + (lid >> 2) + rh * 8;
                        float ds = sqR[lrow] + sqc - sc2 * scR[lrow] * (float)C[mi][ni][rh * 2 + cb];
                        int gi = rowBase + lrow;
                        if (tc == tgtR[lrow]) ins_max(pv1, pi1, pv2, pi2, ds, gi);
                        else                  ins_min(nv1, ni1, nv2, ni2, ds, gi);
                    }
                }
                SHFL_MERGE2(ins_max, pv1, pi1, pv2, pi2, 4);
                SHFL_MERGE2(ins_max, pv1, pi1, pv2, pi2, 8);
                SHFL_MERGE2(ins_max, pv1, pi1, pv2, pi2, 16);
                SHFL_MERGE2(ins_min, nv1, ni1, nv2, ni2, 4);
                SHFL_MERGE2(ins_min, nv1, ni1, nv2, ni2, 8);
                SHFL_MERGE2(ins_min, nv1, ni1, nv2, ni2, 16);
                if (lid < 4) {
                    cPV[wy][0][lcol] = pv1; cPI[wy][0][lcol] = pi1;
                    cPV[wy][1][lcol] = pv2; cPI[wy][1][lcol] = pi2;
                    cNV[wy][0][lcol] = nv1; cNI[wy][0][lcol] = ni1;
                    cNV[wy][1][lcol] = nv2; cNI[wy][1][lcol] = ni2;
                }
            }
        }
        __syncthreads();
        if (t < 128) {
            float pv1 = -1e30f, pv2 = -1e30f; int pi1 = IINF, pi2 = IINF;
            float nv1 =  1e30f, nv2 =  1e30f; int ni1 = IINF, ni2 = IINF;
#pragma unroll
            for (int s = 0; s < 2; s++)
#pragma unroll
                for (int e = 0; e < 2; e++) {
                    ins_max(pv1, pi1, pv2, pi2, cPV[s][e][t], cPI[s][e][t]);
                    ins_min(nv1, ni1, nv2, ni2, cNV[s][e][t], cNI[s][e][t]);
                }
            int r = colBase + t;
            g_posVal[(by * 2 + 0) * N + r] = pv1; g_posIdx[(by * 2 + 0) * N + r] = pi1;
            g_posVal[(by * 2 + 1) * N + r] = pv2; g_posIdx[(by * 2 + 1) * N + r] = pi2;
            g_negVal[(by * 2 + 0) * N + r] = nv1; g_negIdx[(by * 2 + 0) * N + r] = ni1;
            g_negVal[(by * 2 + 1) * N + r] = nv2; g_negIdx[(by * 2 + 1) * N + r] = ni2;
        }
    }
}

// ---------------- kernel 3: top-4 select + exact fp32 refine + local --------
__device__ __forceinline__ float warpDot(const float* a, const float* b, int lane) {
    float s = 0.f;
    for (int k = lane * 4; k < D; k += 128) {
        float4 x = *(const float4*)(a + k);
        float4 y = *(const float4*)(b + k);
        s += x.x * y.x + x.y * y.y + x.z * y.z + x.w * y.w;
    }
#pragma unroll
    for (int off = 16; off > 0; off >>= 1)
        s += __shfl_xor_sync(0xffffffffu, s, off);
    return s;
}

__global__ void finalize_rows(const float* __restrict__ X, const float* __restrict__ XL) {
    int warp = (blockIdx.x * blockDim.x + threadIdx.x) >> 5;
    int lane = threadIdx.x & 31;
    if (warp >= N) return;
    int row = warp;

    float pv[2], nvv[2]; int pidx[2], nidx[2];
#pragma unroll
    for (int e = 0; e < 2; e++) {
        pv[e]   = g_posVal[(lane * 2 + e) * N + row];
        pidx[e] = g_posIdx[(lane * 2 + e) * N + row];
        nvv[e]  = g_negVal[(lane * 2 + e) * N + row];
        nidx[e] = g_negIdx[(lane * 2 + e) * N + row];
    }

    int nsel[4];
#pragma unroll
    for (int it = 0; it < 4; it++) {
        float bv = 1e30f; int bi = IINF;
#pragma unroll
        for (int e = 0; e < 2; e++)
            if (nvv[e] < bv || (nvv[e] == bv && nidx[e] < bi)) { bv = nvv[e]; bi = nidx[e]; }
#pragma unroll
        for (int off = 16; off > 0; off >>= 1) {
            float ov = __shfl_xor_sync(0xffffffffu, bv, off);
            int   oi = __shfl_xor_sync(0xffffffffu, bi, off);
            if (ov < bv || (ov == bv && oi < bi)) { bv = ov; bi = oi; }
        }
        nsel[it] = bi;
#pragma unroll
        for (int e = 0; e < 2; e++)
            if (nidx[e] == bi) { nvv[e] = 1e30f; nidx[e] = IINF; }
    }
    int psel[4];
#pragma unroll
    for (int it = 0; it < 4; it++) {
        float bv = -1e30f; int bi = IINF;
#pragma unroll
        for (int e = 0; e < 2; e++)
            if (pv[e] > bv || (pv[e] == bv && pidx[e] < bi)) { bv = pv[e]; bi = pidx[e]; }
#pragma unroll
        for (int off = 16; off > 0; off >>= 1) {
            float ov = __shfl_xor_sync(0xffffffffu, bv, off);
            int   oi = __shfl_xor_sync(0xffffffffu, bi, off);
            if (ov > bv || (ov == bv && oi < bi)) { bv = ov; bi = oi; }
        }
        psel[it] = bi;
#pragma unroll
        for (int e = 0; e < 2; e++)
            if (pidx[e] == bi) { pv[e] = -1e30f; pidx[e] = IINF; }
    }

    const float* xr = X + (size_t)row * D;
    float sqr = g_sq[row];
    float bestPd = -1e30f; int bestPi = IINF;
#pragma unroll
    for (int it = 0; it < 4; it++) {
        int j = psel[it];
        if (j < 0 || j >= N) continue;
        float dot = warpDot(xr, X + (size_t)j * D, lane);
        float d = sqrtf(fmaxf(sqr + g_sq[j] - 2.f * dot, EPSC));
        if (d > bestPd || (d == bestPd && j < bestPi)) { bestPd = d; bestPi = j; }
    }
    float bestNd = 1e30f; int bestNi = IINF;
#pragma unroll
    for (int it = 0; it < 4; it++) {
        int j = nsel[it];
        if (j < 0 || j >= N) continue;
        float dot = warpDot(xr, X + (size_t)j * D, lane);
        float d = sqrtf(fmaxf(sqr + g_sq[j] - 2.f * dot, EPSC));
        if (d < bestNd || (d == bestNd && j < bestNi)) { bestNd = d; bestNi = j; }
    }
    int pi = (bestPi < 0 || bestPi >= N) ? row : bestPi;
    int ni = (bestNi < 0 || bestNi >= N) ? row : bestNi;

    const float* li = XL + (size_t)row * DL;
    const float* lp = XL + (size_t)pi  * DL;
    const float* ln = XL + (size_t)ni  * DL;
    float dp = 0.f, dn = 0.f;
    for (int k = lane * 4; k < DL; k += 128) {
        float4 a = *(const float4*)(li + k);
        float4 b = *(const float4*)(lp + k);
        float4 c = *(const float4*)(ln + k);
        dp += a.x * b.x + a.y * b.y + a.z * b.z + a.w * b.w;
        dn += a.x * c.x + a.y * c.y + a.z * c.z + a.w * c.w;
    }
#pragma unroll
    for (int off = 16; off > 0; off >>= 1) {
        dp += __shfl_xor_sync(0xffffffffu, dp, off);
        dn += __shfl_xor_sync(0xffffffffu, dn, off);
    }
    if (lane == 0) {
        float lap = sqrtf(fmaxf(g_lsq[row] + g_lsq[pi] - 2.f * dp, EPSC));
        float lan = sqrtf(fmaxf(g_lsq[row] + g_lsq[ni] - 2.f * dn, EPSC));
        g_rowLoss[row]  = fmaxf(0.f, bestPd - bestNd + MARGIN);
        g_rowLocal[row] = fmaxf(0.f, lap - lan + MARGIN);
    }
}

// ---------------- kernel 4: deterministic means ----------------
__global__ void final_reduce(float* __restrict__ out, int out_size) {
    __shared__ float s1[256], s2[256];
    int t = threadIdx.x;
    float a = 0.f, b = 0.f;
    for (int i = t; i < N; i += 256) { a += g_rowLoss[i]; b += g_rowLocal[i]; }
    s1[t] = a; s2[t] = b;
    __syncthreads();
    for (int off = 128; off > 0; off >>= 1) {
        if (t < off) { s1[t] += s1[t + off]; s2[t] += s2[t + off]; }
        __syncthreads();
    }
    if (t == 0) {
        out[0] = s1[0] / (float)N;
        if (out_size > 1) out[1] = s2[0] / (float)N;
    }
}

// ---------------- launch ----------------
extern "C" void kernel_launch(void* const* d_in, const int* in_sizes, int n_in,
                              void* d_out, int out_size) {
    const float* X  = (const float*)d_in[0];
    const float* XL = (const float*)d_in[1];
    const int*   T  = (const int*)d_in[2];
    (void)in_sizes; (void)n_in;

    cudaFuncSetAttribute(gram_mma_kernel,
                         cudaFuncAttributeMaxDynamicSharedMemorySize, DYN_B);

    prep_targets<<<1, 1024>>>(T);
    quant_kernel<<<2 * N, 256>>>(X, XL);
    gram_mma_kernel<<<NBLK, 256, DYN_B>>>();
    finalize_rows<<<N / 8, 256>>>(X, XL);
    final_reduce<<<1, 256>>>((float*)d_out, out_size);
}